// round 13
// baseline (speedup 1.0000x reference)
#include <cuda_runtime.h>

#define BB 8
#define NN 1024
#define HIDD 256
#define HEADS 8
#define DHH 32
#define EPER 16384
#define KKP 512

// ---- output layout (float32, concatenated flattened outputs) ----
#define OFF_ENC   0
#define OFF_SUBX  (BB*NN*HIDD)
#define OFF_EDGE  (OFF_SUBX + BB*KKP*HIDD)
#define OFF_PERM  (OFF_EDGE + BB*2*EPER)
#define OFF_VALID (OFF_PERM + BB*KKP)

// ---- device scratch ----
__device__ float g_Q[BB*NN*HIDD];
__device__ float g_K[BB*NN*HIDD];
__device__ float g_V[BB*NN*HIDD];
__device__ float g_AO[BB*NN*HIDD];
__device__ float g_ENC[BB*NN*HIDD];
__device__ float g_score[BB*NN];
__device__ int   g_perm[BB*KKP];
__device__ float g_vals[BB*KKP];
__device__ int   g_nodemap[BB*NN];
__device__ unsigned long long g_es[BB*EPER];

// ---- packed f32x2 helpers ----
__device__ __forceinline__ unsigned long long fma2(
    unsigned long long a, unsigned long long b, unsigned long long c) {
    unsigned long long d;
    asm("fma.rn.f32x2 %0, %1, %2, %3;" : "=l"(d) : "l"(a), "l"(b), "l"(c));
    return d;
}
__device__ __forceinline__ unsigned long long mul2(
    unsigned long long a, unsigned long long b) {
    unsigned long long d;
    asm("mul.rn.f32x2 %0, %1, %2;" : "=l"(d) : "l"(a), "l"(b));
    return d;
}
__device__ __forceinline__ unsigned long long pack2(float lo, float hi) {
    unsigned long long r;
    asm("mov.b64 %0, {%1, %2};" : "=l"(r) : "f"(lo), "f"(hi));
    return r;
}
__device__ __forceinline__ float2 unpack2(unsigned long long v) {
    float2 r;
    asm("mov.b64 {%0, %1}, %2;" : "=f"(r.x), "=f"(r.y) : "l"(v));
    return r;
}
__device__ __forceinline__ void cp16(unsigned smem, const void* g) {
    asm volatile("cp.async.cg.shared.global [%0], [%1], 16;" :: "r"(smem), "l"(g));
}
__device__ __forceinline__ void cp_commit() {
    asm volatile("cp.async.commit_group;");
}
__device__ __forceinline__ void cp_wait0() {
    asm volatile("cp.async.wait_group 0;");
}

// ============================================================
// GEMM: C[8192,256] = A[8192,256] @ W[256,256]
// 128x128 block tile, 256 threads, 8x8 microtile.
// Rows vectorized in f32x2 pairs (A read as natural row pairs,
// broadcast LDS.128); W pre-duplicated (w,w) in lane-interleaved
// smem Ws2[k][c][tx] -> conflict-free LDS.64, 1 wavefront each.
// Each C element sums over k ascending: bit-identical to r4-r10.
// ============================================================
__global__ __launch_bounds__(256) void gemm_k(
    const float* __restrict__ Xp, const float* __restrict__ W0,
    const float* __restrict__ W1, const float* __restrict__ W2,
    int sel_base, float* __restrict__ out2)
{
    const int sel = sel_base + blockIdx.z;
    const float* A;
    const float* W;
    float* C;
    if      (sel == 0) { A = Xp;   W = W0; C = g_Q; }
    else if (sel == 1) { A = Xp;   W = W1; C = g_K; }
    else if (sel == 2) { A = Xp;   W = W2; C = g_V; }
    else               { A = g_AO; W = W0; C = g_ENC; }

    __shared__ float  As[16][128];        // 8KB, [k][row]
    __shared__ float2 Ws2[16][8][16];     // 16KB, [k][colgrp][tx] duplicated

    const int t   = threadIdx.x;
    const int tx8 = t & 15;               // lane col id
    const int ty  = t >> 4;               // row group (8 rows each)
    const int rowBase = blockIdx.y * 128;
    const int colBase = blockIdx.x * 128;

    unsigned long long acc[8][4];         // [colgrp][rowpair]
    #pragma unroll
    for (int c = 0; c < 8; c++)
        #pragma unroll
        for (int rp = 0; rp < 4; rp++) acc[c][rp] = 0ull;

    // A staging (identical index scheme to round 10)
    const int ar0 = (t * 2) >> 2,     ac0 = ((t * 2) & 3) << 2;
    const int ar1 = (t * 2 + 1) >> 2, ac1 = ((t * 2 + 1) & 3) << 2;
    // W staging: row wr = ty, cols c*16 + tx8
    const int wr = ty;

    // prologue: chunk 0 into registers
    float4 aR0 = *(const float4*)(A + (rowBase + ar0) * 256 + ac0);
    float4 aR1 = *(const float4*)(A + (rowBase + ar1) * 256 + ac1);
    float wP[8];
    #pragma unroll
    for (int c = 0; c < 8; c++)
        wP[c] = W[wr * 256 + colBase + c * 16 + tx8];

    for (int k0 = 0; k0 < 256; k0 += 16) {
        As[ac0 + 0][ar0] = aR0.x; As[ac0 + 1][ar0] = aR0.y;
        As[ac0 + 2][ar0] = aR0.z; As[ac0 + 3][ar0] = aR0.w;
        As[ac1 + 0][ar1] = aR1.x; As[ac1 + 1][ar1] = aR1.y;
        As[ac1 + 2][ar1] = aR1.z; As[ac1 + 3][ar1] = aR1.w;
        #pragma unroll
        for (int c = 0; c < 8; c++)
            Ws2[wr][c][tx8] = make_float2(wP[c], wP[c]);
        __syncthreads();
        if (k0 < 240) {   // prefetch next chunk while computing
            aR0 = *(const float4*)(A + (rowBase + ar0) * 256 + k0 + 16 + ac0);
            aR1 = *(const float4*)(A + (rowBase + ar1) * 256 + k0 + 16 + ac1);
            #pragma unroll
            for (int c = 0; c < 8; c++)
                wP[c] = W[(k0 + 16 + wr) * 256 + colBase + c * 16 + tx8];
        }
        #pragma unroll
        for (int kk = 0; kk < 16; kk++) {
            const ulonglong2* ap = (const ulonglong2*)&As[kk][ty << 3];
            ulonglong2 a01 = ap[0], a23 = ap[1];
            unsigned long long ar[4] = { a01.x, a01.y, a23.x, a23.y };
            #pragma unroll
            for (int c = 0; c < 8; c++) {
                unsigned long long w2 =
                    *(const unsigned long long*)&Ws2[kk][c][tx8];
                acc[c][0] = fma2(ar[0], w2, acc[c][0]);
                acc[c][1] = fma2(ar[1], w2, acc[c][1]);
                acc[c][2] = fma2(ar[2], w2, acc[c][2]);
                acc[c][3] = fma2(ar[3], w2, acc[c][3]);
            }
        }
        __syncthreads();
    }

    #pragma unroll
    for (int rp = 0; rp < 4; rp++) {
        int row0 = rowBase + (ty << 3) + rp * 2;
        #pragma unroll
        for (int c = 0; c < 8; c++) {
            float2 v = unpack2(acc[c][rp]);
            int col = colBase + c * 16 + tx8;
            C[(long)row0 * 256 + col]       = v.x;
            C[(long)(row0 + 1) * 256 + col] = v.y;
            if (sel == 3) {
                out2[(long)row0 * 256 + col]       = v.x;
                out2[(long)(row0 + 1) * 256 + col] = v.y;
            }
        }
    }
}

// ============================================================
// Attention: round-7 formulation VERBATIM (best measured: 279us;
// math frozen — feeds the top-k selection knife-edge).
// ============================================================
__global__ __launch_bounds__(256, 1) void attn_kernel(const float* __restrict__ dist)
{
    __shared__ float Ks[2][8 * 256];
    __shared__ float Vs[2][8 * 256];
    __shared__ float ds[2][8 * 64];   // [k][q] transposed

    const int b = blockIdx.y;
    const int qbase = blockIdx.x * 64;
    const int t = threadIdx.x;
    const int h = t >> 5, q = t & 31;
    const int drow = t >> 2, dcol = (t & 3) << 1;

    const float* Kg = g_K + (long)b * NN * HIDD;
    const float* Vg = g_V + (long)b * NN * HIDD;
    const float* dg = dist + ((long)(b * NN + qbase + drow)) * NN + dcol;

    unsigned ks_base = (unsigned)__cvta_generic_to_shared(&Ks[0][0]);
    unsigned vs_base = (unsigned)__cvta_generic_to_shared(&Vs[0][0]);

    unsigned long long qa[16], qb[16];
    {
        const ulonglong2* qp0 = (const ulonglong2*)(g_Q + ((long)(b * NN + qbase + q)) * HIDD + (h << 5));
        const ulonglong2* qp1 = (const ulonglong2*)(g_Q + ((long)(b * NN + qbase + q + 32)) * HIDD + (h << 5));
        #pragma unroll
        for (int d4 = 0; d4 < 8; d4++) {
            ulonglong2 v0 = qp0[d4], v1 = qp1[d4];
            qa[2*d4] = v0.x; qa[2*d4+1] = v0.y;
            qb[2*d4] = v1.x; qb[2*d4+1] = v1.y;
        }
    }

    {
        cp16(ks_base + t * 16,             (const char*)Kg + t * 16);
        cp16(ks_base + (t + 256) * 16,     (const char*)Kg + (t + 256) * 16);
        cp16(vs_base + t * 16,             (const char*)Vg + t * 16);
        cp16(vs_base + (t + 256) * 16,     (const char*)Vg + (t + 256) * 16);
        cp_commit();
        float2 d0 = *(const float2*)dg;
        ds[0][dcol * 64 + drow]       = d0.x;
        ds[0][(dcol + 1) * 64 + drow] = d0.y;
        cp_wait0();
    }
    __syncthreads();

    float ma = -1e30f, la = 0.f, mb = -1e30f, lb = 0.f;
    unsigned long long oa[16], ob[16];
    #pragma unroll
    for (int d = 0; d < 16; d++) { oa[d] = 0ull; ob[d] = 0ull; }
    const float scale = 0.1767766952966369f;  // 1/sqrt(32)

    for (int kt = 0; kt < 128; kt++) {
        const int cur = kt & 1;
        float2 pd;
        if (kt < 127) {
            const int nxt = cur ^ 1;
            const char* Kn = (const char*)Kg + (kt + 1) * 8192;
            const char* Vn = (const char*)Vg + (kt + 1) * 8192;
            unsigned ksn = ks_base + nxt * 8192;
            unsigned vsn = vs_base + nxt * 8192;
            cp16(ksn + t * 16,         Kn + t * 16);
            cp16(ksn + (t + 256) * 16, Kn + (t + 256) * 16);
            cp16(vsn + t * 16,         Vn + t * 16);
            cp16(vsn + (t + 256) * 16, Vn + (t + 256) * 16);
            cp_commit();
            pd = *(const float2*)(dg + (kt + 1) * 8);
        }

        const float* Kc = Ks[cur];
        const float* Vc = Vs[cur];
        const float* dc = ds[cur];

        float sva[8], svb[8];
        float smaxa = -1e30f, smaxb = -1e30f;
        #pragma unroll
        for (int kk = 0; kk < 8; kk++) {
            const ulonglong2* kp = (const ulonglong2*)(Kc + kk * 256 + (h << 5));
            unsigned long long accA = 0ull, accB = 0ull, accC = 0ull, accD = 0ull;
            #pragma unroll
            for (int d4 = 0; d4 < 8; d4++) {
                ulonglong2 k2 = kp[d4];
                accA = fma2(qa[2*d4],   k2.x, accA);
                accB = fma2(qa[2*d4+1], k2.y, accB);
                accC = fma2(qb[2*d4],   k2.x, accC);
                accD = fma2(qb[2*d4+1], k2.y, accD);
            }
            float2 fa = unpack2(accA), fb = unpack2(accB);
            float2 fc = unpack2(accC), fd = unpack2(accD);
            float sA = ((fa.x + fa.y) + (fb.x + fb.y)) * scale + dc[kk * 64 + q];
            float sB = ((fc.x + fc.y) + (fd.x + fd.y)) * scale + dc[kk * 64 + 32 + q];
            sva[kk] = sA; svb[kk] = sB;
            smaxa = fmaxf(smaxa, sA);
            smaxb = fmaxf(smaxb, sB);
        }
        float mna = fmaxf(ma, smaxa);
        if (__any_sync(0xFFFFFFFFu, mna > ma)) {
            float corr = __expf(ma - mna);
            la *= corr;
            unsigned long long cc = pack2(corr, corr);
            #pragma unroll
            for (int d = 0; d < 16; d++) oa[d] = mul2(oa[d], cc);
            ma = mna;
        }
        float mnb = fmaxf(mb, smaxb);
        if (__any_sync(0xFFFFFFFFu, mnb > mb)) {
            float corr = __expf(mb - mnb);
            lb *= corr;
            unsigned long long cc = pack2(corr, corr);
            #pragma unroll
            for (int d = 0; d < 16; d++) ob[d] = mul2(ob[d], cc);
            mb = mnb;
        }
        #pragma unroll
        for (int kk = 0; kk < 8; kk++) {
            float pA = __expf(sva[kk] - ma);
            float pB = __expf(svb[kk] - mb);
            la += pA; lb += pB;
            unsigned long long p2a = pack2(pA, pA);
            unsigned long long p2b = pack2(pB, pB);
            const ulonglong2* vp = (const ulonglong2*)(Vc + kk * 256 + (h << 5));
            #pragma unroll
            for (int d4 = 0; d4 < 8; d4++) {
                ulonglong2 v2 = vp[d4];
                oa[2*d4]   = fma2(v2.x, p2a, oa[2*d4]);
                oa[2*d4+1] = fma2(v2.y, p2a, oa[2*d4+1]);
                ob[2*d4]   = fma2(v2.x, p2b, ob[2*d4]);
                ob[2*d4+1] = fma2(v2.y, p2b, ob[2*d4+1]);
            }
        }

        if (kt < 127) {
            const int nxt = cur ^ 1;
            ds[nxt][dcol * 64 + drow]       = pd.x;
            ds[nxt][(dcol + 1) * 64 + drow] = pd.y;
            cp_wait0();
        }
        __syncthreads();
    }

    float inva = 1.f / la, invb = 1.f / lb;
    float* op0 = g_AO + ((long)(b * NN + qbase + q)) * HIDD + (h << 5);
    float* op1 = g_AO + ((long)(b * NN + qbase + q + 32)) * HIDD + (h << 5);
    #pragma unroll
    for (int d4 = 0; d4 < 8; d4++) {
        float2 a0 = unpack2(oa[2*d4]), a1 = unpack2(oa[2*d4+1]);
        float2 b0 = unpack2(ob[2*d4]), b1 = unpack2(ob[2*d4+1]);
        ((float4*)op0)[d4] = make_float4(a0.x * inva, a0.y * inva, a1.x * inva, a1.y * inva);
        ((float4*)op1)[d4] = make_float4(b0.x * invb, b0.y * invb, b1.x * invb, b1.y * invb);
    }
}

// ============================================================
// Node scores: s = tanh((x . w) / ||w||). One warp per node.
// ============================================================
__global__ __launch_bounds__(256) void score_kernel(const float* __restrict__ w)
{
    int warp = (blockIdx.x * blockDim.x + threadIdx.x) >> 5;
    int lane = threadIdx.x & 31;
    if (warp >= BB * NN) return;
    const float* x = g_ENC + (long)warp * HIDD;
    float sx = 0.f, sw = 0.f;
    #pragma unroll
    for (int i = lane; i < HIDD; i += 32) {
        float wv = w[i];
        sx += x[i] * wv;
        sw += wv * wv;
    }
    #pragma unroll
    for (int off = 16; off; off >>= 1) {
        sx += __shfl_xor_sync(0xFFFFFFFFu, sx, off);
        sw += __shfl_xor_sync(0xFFFFFFFFu, sw, off);
    }
    if (lane == 0) g_score[warp] = tanhf(sx / sqrtf(sw));
}

// ============================================================
// Top-K per graph: bitonic sort of 1024 (desc score, asc index).
// ============================================================
__global__ __launch_bounds__(1024) void topk_kernel(float* __restrict__ out_perm)
{
    __shared__ unsigned long long s[NN];
    const int b = blockIdx.x, t = threadIdx.x;
    float sc = g_score[b * NN + t];
    unsigned u = __float_as_uint(sc);
    u = (u & 0x80000000u) ? ~u : (u | 0x80000000u);
    u = ~u;                                            // descending
    s[t] = (((unsigned long long)u) << 32) | (unsigned)t;
    g_nodemap[b * NN + t] = -1;
    __syncthreads();
    for (unsigned k = 2; k <= NN; k <<= 1)
        for (unsigned j = k >> 1; j; j >>= 1) {
            unsigned i = t, ixj = i ^ j;
            if (ixj > i) {
                bool up = ((i & k) == 0);
                unsigned long long a = s[i], c = s[ixj];
                if ((a > c) == up) { s[i] = c; s[ixj] = a; }
            }
            __syncthreads();
        }
    if (t < KKP) {
        int node = (int)(s[t] & 0xFFFFFFFFu);
        g_perm[b * KKP + t] = node;
        g_vals[b * KKP + t] = g_score[b * NN + node];
        out_perm[b * KKP + t] = (float)node;
        g_nodemap[b * NN + node] = t;
    }
}

// ============================================================
// sub_x gather
// ============================================================
__global__ __launch_bounds__(256) void subx_kernel(float* __restrict__ out)
{
    const int row = blockIdx.x;
    const int b = row / KKP;
    const int node = g_perm[row];
    const float val = g_vals[row];
    const float* src = g_ENC + ((long)b * NN + node) * HIDD;
    out[(long)row * HIDD + threadIdx.x] = src[threadIdx.x] * val;
}

// ============================================================
// Edge pipeline (5 kernels): build+segsort, gmerge(8192),
// smerge(8192), quadmerge(16384 j=8192+4096), smerge+emit.
// ============================================================
__global__ __launch_bounds__(1024) void edge_sortbuild(const void* __restrict__ eiraw)
{
    __shared__ unsigned long long sh[4096];
    __shared__ int s_is64;
    const int b = blockIdx.x >> 2, seg = blockIdx.x & 3;
    const int t = threadIdx.x;
    if (t == 0) {
        const unsigned* w32 = (const unsigned*)eiraw;
        int all0 = 1;
        for (int i = 0; i < 64; i++)
            if (w32[2 * i + 1] != 0u) { all0 = 0; break; }
        s_is64 = all0;
    }
    __syncthreads();
    const int is64 = s_is64;
    const int total = BB * EPER;

    #pragma unroll
    for (int li = 0; li < 4; li++) {
        int i = t + li * 1024;
        int idx = b * EPER + seg * 4096 + i;
        long long vs, vd;
        if (is64) {
            const long long* ei = (const long long*)eiraw;
            vs = ei[idx];
            vd = ei[total + idx];
        } else {
            const int* ei = (const int*)eiraw;
            vs = ei[idx];
            vd = ei[total + idx];
        }
        int src = (int)(vs - (long long)b * NN);
        int dst = (int)(vd - (long long)b * NN);
        src = min(max(src, 0), NN - 1);
        dst = min(max(dst, 0), NN - 1);
        int nu = g_nodemap[b * NN + src];
        int nv = g_nodemap[b * NN + dst];
        bool valid = (nu >= 0) && (nv >= 0);
        unsigned key = valid ? (unsigned)(nu * KKP + nv) : (unsigned)(KKP * KKP);
        int ou = valid ? nu : -1, ov = valid ? nv : -1;
        sh[i] = (((unsigned long long)key) << 21)
              | (((unsigned long long)(ou + 1)) << 11)
              | (((unsigned long long)(ov + 1)) << 1)
              | (valid ? 1ull : 0ull);
    }
    __syncthreads();

    for (unsigned k = 2; k <= 4096; k <<= 1)
        for (unsigned j = k >> 1; j; j >>= 1) {
            for (int loc = t; loc < 4096; loc += 1024) {
                unsigned i2 = (unsigned)loc, ixj = i2 ^ j;
                if (ixj > i2) {
                    unsigned gi = seg * 4096 + i2;
                    bool up = ((gi & k) == 0);
                    unsigned long long a = sh[i2], c = sh[ixj];
                    if ((a > c) == up) { sh[i2] = c; sh[ixj] = a; }
                }
            }
            __syncthreads();
        }
    unsigned long long* es = g_es + (long)b * EPER + seg * 4096;
    for (int i = t; i < 4096; i += 1024) es[i] = sh[i];
}

__global__ __launch_bounds__(1024) void edge_gmerge(unsigned k, unsigned j)
{
    int loc = blockIdx.x * blockDim.x + threadIdx.x;
    unsigned i = (unsigned)(loc & (EPER - 1));
    int b = loc >> 14;
    unsigned ixj = i ^ j;
    if (ixj > i) {
        unsigned long long* es = g_es + (long)b * EPER;
        bool up = ((i & k) == 0);
        unsigned long long a = es[i], c = es[ixj];
        if ((a > c) == up) { es[i] = c; es[ixj] = a; }
    }
}

// k=16384 steps j=8192 and j=4096 fused (all directions ascending).
__global__ __launch_bounds__(1024) void edge_quadmerge()
{
    const int b = blockIdx.x >> 2, seg = blockIdx.x & 3;
    const int i0 = seg * 1024 + threadIdx.x;
    unsigned long long* es = g_es + (long)b * EPER;
    unsigned long long v0 = es[i0];
    unsigned long long v1 = es[i0 + 4096];
    unsigned long long v2 = es[i0 + 8192];
    unsigned long long v3 = es[i0 + 12288];
    unsigned long long w;
    if (v0 > v2) { w = v0; v0 = v2; v2 = w; }   // j = 8192
    if (v1 > v3) { w = v1; v1 = v3; v3 = w; }
    if (v0 > v1) { w = v0; v0 = v1; v1 = w; }   // j = 4096
    if (v2 > v3) { w = v2; v2 = v3; v3 = w; }
    es[i0]         = v0;
    es[i0 + 4096]  = v1;
    es[i0 + 8192]  = v2;
    es[i0 + 12288] = v3;
}

__global__ __launch_bounds__(1024) void edge_smerge(unsigned k)
{
    __shared__ unsigned long long sh[4096];
    const int b = blockIdx.x >> 2, seg = blockIdx.x & 3;
    const int t = threadIdx.x;
    unsigned long long* es = g_es + (long)b * EPER + seg * 4096;
    for (int i = t; i < 4096; i += 1024) sh[i] = es[i];
    __syncthreads();
    for (unsigned j = 2048; j; j >>= 1) {
        for (int loc = t; loc < 4096; loc += 1024) {
            unsigned i2 = (unsigned)loc, ixj = i2 ^ j;
            if (ixj > i2) {
                unsigned gi = seg * 4096 + i2;
                bool up = ((gi & k) == 0);
                unsigned long long a = sh[i2], c = sh[ixj];
                if ((a > c) == up) { sh[i2] = c; sh[ixj] = a; }
            }
        }
        __syncthreads();
    }
    for (int i = t; i < 4096; i += 1024) es[i] = sh[i];
}

// Final merge tail (k = 16384, j = 2048..1) fused with emit.
__global__ __launch_bounds__(1024) void edge_smerge_emit(
    float* __restrict__ out_e, float* __restrict__ out_valid)
{
    __shared__ unsigned long long sh[4096];
    const int b = blockIdx.x >> 2, seg = blockIdx.x & 3;
    const int t = threadIdx.x;
    const unsigned k = 16384u;
    unsigned long long* es = g_es + (long)b * EPER + seg * 4096;
    for (int i = t; i < 4096; i += 1024) sh[i] = es[i];
    __syncthreads();
    for (unsigned j = 2048; j; j >>= 1) {
        for (int loc = t; loc < 4096; loc += 1024) {
            unsigned i2 = (unsigned)loc, ixj = i2 ^ j;
            if (ixj > i2) {
                unsigned gi = seg * 4096 + i2;
                bool up = ((gi & k) == 0);
                unsigned long long a = sh[i2], c = sh[ixj];
                if ((a > c) == up) { sh[i2] = c; sh[ixj] = a; }
            }
        }
        __syncthreads();
    }
    for (int i = t; i < 4096; i += 1024) {
        unsigned long long p = sh[i];
        int e = seg * 4096 + i;
        int ou = (int)((p >> 11) & 0x3FFu) - 1;
        int ov = (int)((p >> 1) & 0x3FFu) - 1;
        out_e[(long)b * 2 * EPER + e]        = (float)ou;
        out_e[(long)b * 2 * EPER + EPER + e] = (float)ov;
        out_valid[(long)b * EPER + e]        = (float)(p & 1ull);
    }
}

// ============================================================
extern "C" void kernel_launch(void* const* d_in, const int* in_sizes, int n_in,
                              void* d_out, int out_size)
{
    const float* X    = (const float*)d_in[0];
    const void*  EI   = d_in[1];
    const float* DIST = (const float*)d_in[3];
    const float* Wq   = (const float*)d_in[5];
    const float* Wk   = (const float*)d_in[6];
    const float* Wv   = (const float*)d_in[7];
    const float* Wo   = (const float*)d_in[8];
    const float* tw   = (const float*)d_in[9];
    float* out = (float*)d_out;

    gemm_k<<<dim3(2, 64, 3), 256>>>(X, Wq, Wk, Wv, 0, out + OFF_ENC);

    attn_kernel<<<dim3(16, 8), 256>>>(DIST);

    gemm_k<<<dim3(2, 64, 1), 256>>>(X, Wo, Wo, Wo, 3, out + OFF_ENC);

    score_kernel<<<(BB * NN * 32) / 256, 256>>>(tw);
    topk_kernel<<<BB, NN>>>(out + OFF_PERM);
    subx_kernel<<<BB * KKP, 256>>>(out + OFF_SUBX);

    edge_sortbuild<<<32, 1024>>>(EI);
    edge_gmerge<<<128, 1024>>>(8192u, 4096u);
    edge_smerge<<<32, 1024>>>(8192u);
    edge_quadmerge<<<32, 1024>>>();
    edge_smerge_emit<<<32, 1024>>>(out + OFF_EDGE, out + OFF_VALID);
}

// round 14
// speedup vs baseline: 1.0645x; 1.0645x over previous
#include <cuda_runtime.h>

#define BB 8
#define NN 1024
#define HIDD 256
#define HEADS 8
#define DHH 32
#define EPER 16384
#define KKP 512

// ---- output layout (float32, concatenated flattened outputs) ----
#define OFF_ENC   0
#define OFF_SUBX  (BB*NN*HIDD)
#define OFF_EDGE  (OFF_SUBX + BB*KKP*HIDD)
#define OFF_PERM  (OFF_EDGE + BB*2*EPER)
#define OFF_VALID (OFF_PERM + BB*KKP)

// ---- device scratch ----
__device__ float g_Q[BB*NN*HIDD];
__device__ float g_K[BB*NN*HIDD];
__device__ float g_V[BB*NN*HIDD];
__device__ float g_AO[BB*NN*HIDD];
__device__ float g_ENC[BB*NN*HIDD];
__device__ float g_score[BB*NN];
__device__ int   g_perm[BB*KKP];
__device__ float g_vals[BB*KKP];
__device__ int   g_nodemap[BB*NN];
__device__ unsigned long long g_es[BB*EPER];

// ---- packed f32x2 helpers ----
__device__ __forceinline__ unsigned long long fma2(
    unsigned long long a, unsigned long long b, unsigned long long c) {
    unsigned long long d;
    asm("fma.rn.f32x2 %0, %1, %2, %3;" : "=l"(d) : "l"(a), "l"(b), "l"(c));
    return d;
}
__device__ __forceinline__ unsigned long long mul2(
    unsigned long long a, unsigned long long b) {
    unsigned long long d;
    asm("mul.rn.f32x2 %0, %1, %2;" : "=l"(d) : "l"(a), "l"(b));
    return d;
}
__device__ __forceinline__ unsigned long long pack2(float lo, float hi) {
    unsigned long long r;
    asm("mov.b64 %0, {%1, %2};" : "=l"(r) : "f"(lo), "f"(hi));
    return r;
}
__device__ __forceinline__ float2 unpack2(unsigned long long v) {
    float2 r;
    asm("mov.b64 {%0, %1}, %2;" : "=f"(r.x), "=f"(r.y) : "l"(v));
    return r;
}
__device__ __forceinline__ void cp16(unsigned smem, const void* g) {
    asm volatile("cp.async.cg.shared.global [%0], [%1], 16;" :: "r"(smem), "l"(g));
}
__device__ __forceinline__ void cp_commit() {
    asm volatile("cp.async.commit_group;");
}
__device__ __forceinline__ void cp_wait0() {
    asm volatile("cp.async.wait_group 0;");
}

// ============================================================
// GEMM: C[8192,256] = A[8192,256] @ W[256,256]
// Round-10 champion version EXACTLY (pack2 inner loop, 128x64
// tile, no register prefetch). sel 0/1/2 = QKV via gridDim.z,
// sel 3 = Wo with dual write. Numerics frozen.
// ============================================================
__global__ __launch_bounds__(256) void gemm_k(
    const float* __restrict__ Xp, const float* __restrict__ W0,
    const float* __restrict__ W1, const float* __restrict__ W2,
    int sel_base, float* __restrict__ out2)
{
    const int sel = sel_base + blockIdx.z;
    const float* A;
    const float* W;
    float* C;
    if      (sel == 0) { A = Xp;   W = W0; C = g_Q; }
    else if (sel == 1) { A = Xp;   W = W1; C = g_K; }
    else if (sel == 2) { A = Xp;   W = W2; C = g_V; }
    else               { A = g_AO; W = W0; C = g_ENC; }

    __shared__ float As[16][128];
    __shared__ float Ws[16][64];
    const int t  = threadIdx.x;
    const int tx = t & 15;
    const int ty = t >> 4;
    const int rowBase = blockIdx.y * 128;
    const int colBase = blockIdx.x * 64;

    unsigned long long acc2[8][2];
    #pragma unroll
    for (int i = 0; i < 8; i++) { acc2[i][0] = 0ull; acc2[i][1] = 0ull; }

    const int wr = t >> 4, wc = (t & 15) << 2;

    for (int k0 = 0; k0 < 256; k0 += 16) {
        #pragma unroll
        for (int li = 0; li < 2; li++) {
            int idx = t * 2 + li;
            int row = idx >> 2;
            int c4  = (idx & 3) << 2;
            float4 a4 = *(const float4*)(A + (rowBase + row) * 256 + k0 + c4);
            As[c4 + 0][row] = a4.x; As[c4 + 1][row] = a4.y;
            As[c4 + 2][row] = a4.z; As[c4 + 3][row] = a4.w;
        }
        *(float4*)(&Ws[wr][wc]) = *(const float4*)(W + (k0 + wr) * 256 + colBase + wc);
        __syncthreads();
        #pragma unroll
        for (int kk = 0; kk < 16; kk++) {
            float4 a0 = *(const float4*)(&As[kk][ty << 3]);
            float4 a1 = *(const float4*)(&As[kk][(ty << 3) + 4]);
            ulonglong2 w2 = *(const ulonglong2*)(&Ws[kk][tx << 2]);
            unsigned long long b0 = pack2(a0.x, a0.x), b1 = pack2(a0.y, a0.y);
            unsigned long long b2 = pack2(a0.z, a0.z), b3 = pack2(a0.w, a0.w);
            unsigned long long b4 = pack2(a1.x, a1.x), b5 = pack2(a1.y, a1.y);
            unsigned long long b6 = pack2(a1.z, a1.z), b7 = pack2(a1.w, a1.w);
            acc2[0][0] = fma2(b0, w2.x, acc2[0][0]); acc2[0][1] = fma2(b0, w2.y, acc2[0][1]);
            acc2[1][0] = fma2(b1, w2.x, acc2[1][0]); acc2[1][1] = fma2(b1, w2.y, acc2[1][1]);
            acc2[2][0] = fma2(b2, w2.x, acc2[2][0]); acc2[2][1] = fma2(b2, w2.y, acc2[2][1]);
            acc2[3][0] = fma2(b3, w2.x, acc2[3][0]); acc2[3][1] = fma2(b3, w2.y, acc2[3][1]);
            acc2[4][0] = fma2(b4, w2.x, acc2[4][0]); acc2[4][1] = fma2(b4, w2.y, acc2[4][1]);
            acc2[5][0] = fma2(b5, w2.x, acc2[5][0]); acc2[5][1] = fma2(b5, w2.y, acc2[5][1]);
            acc2[6][0] = fma2(b6, w2.x, acc2[6][0]); acc2[6][1] = fma2(b6, w2.y, acc2[6][1]);
            acc2[7][0] = fma2(b7, w2.x, acc2[7][0]); acc2[7][1] = fma2(b7, w2.y, acc2[7][1]);
        }
        __syncthreads();
    }
    #pragma unroll
    for (int i = 0; i < 8; i++) {
        int row = rowBase + (ty << 3) + i;
        float2 lo = unpack2(acc2[i][0]), hi = unpack2(acc2[i][1]);
        float4 v = make_float4(lo.x, lo.y, hi.x, hi.y);
        *(float4*)(C + row * 256 + colBase + (tx << 2)) = v;
        if (sel == 3) *(float4*)(out2 + row * 256 + colBase + (tx << 2)) = v;
    }
}

// ============================================================
// Attention: round-7 formulation VERBATIM (best measured: 279us;
// math frozen — feeds the top-k selection knife-edge).
// ============================================================
__global__ __launch_bounds__(256, 1) void attn_kernel(const float* __restrict__ dist)
{
    __shared__ float Ks[2][8 * 256];
    __shared__ float Vs[2][8 * 256];
    __shared__ float ds[2][8 * 64];   // [k][q] transposed

    const int b = blockIdx.y;
    const int qbase = blockIdx.x * 64;
    const int t = threadIdx.x;
    const int h = t >> 5, q = t & 31;
    const int drow = t >> 2, dcol = (t & 3) << 1;

    const float* Kg = g_K + (long)b * NN * HIDD;
    const float* Vg = g_V + (long)b * NN * HIDD;
    const float* dg = dist + ((long)(b * NN + qbase + drow)) * NN + dcol;

    unsigned ks_base = (unsigned)__cvta_generic_to_shared(&Ks[0][0]);
    unsigned vs_base = (unsigned)__cvta_generic_to_shared(&Vs[0][0]);

    unsigned long long qa[16], qb[16];
    {
        const ulonglong2* qp0 = (const ulonglong2*)(g_Q + ((long)(b * NN + qbase + q)) * HIDD + (h << 5));
        const ulonglong2* qp1 = (const ulonglong2*)(g_Q + ((long)(b * NN + qbase + q + 32)) * HIDD + (h << 5));
        #pragma unroll
        for (int d4 = 0; d4 < 8; d4++) {
            ulonglong2 v0 = qp0[d4], v1 = qp1[d4];
            qa[2*d4] = v0.x; qa[2*d4+1] = v0.y;
            qb[2*d4] = v1.x; qb[2*d4+1] = v1.y;
        }
    }

    {
        cp16(ks_base + t * 16,             (const char*)Kg + t * 16);
        cp16(ks_base + (t + 256) * 16,     (const char*)Kg + (t + 256) * 16);
        cp16(vs_base + t * 16,             (const char*)Vg + t * 16);
        cp16(vs_base + (t + 256) * 16,     (const char*)Vg + (t + 256) * 16);
        cp_commit();
        float2 d0 = *(const float2*)dg;
        ds[0][dcol * 64 + drow]       = d0.x;
        ds[0][(dcol + 1) * 64 + drow] = d0.y;
        cp_wait0();
    }
    __syncthreads();

    float ma = -1e30f, la = 0.f, mb = -1e30f, lb = 0.f;
    unsigned long long oa[16], ob[16];
    #pragma unroll
    for (int d = 0; d < 16; d++) { oa[d] = 0ull; ob[d] = 0ull; }
    const float scale = 0.1767766952966369f;  // 1/sqrt(32)

    for (int kt = 0; kt < 128; kt++) {
        const int cur = kt & 1;
        float2 pd;
        if (kt < 127) {
            const int nxt = cur ^ 1;
            const char* Kn = (const char*)Kg + (kt + 1) * 8192;
            const char* Vn = (const char*)Vg + (kt + 1) * 8192;
            unsigned ksn = ks_base + nxt * 8192;
            unsigned vsn = vs_base + nxt * 8192;
            cp16(ksn + t * 16,         Kn + t * 16);
            cp16(ksn + (t + 256) * 16, Kn + (t + 256) * 16);
            cp16(vsn + t * 16,         Vn + t * 16);
            cp16(vsn + (t + 256) * 16, Vn + (t + 256) * 16);
            cp_commit();
            pd = *(const float2*)(dg + (kt + 1) * 8);
        }

        const float* Kc = Ks[cur];
        const float* Vc = Vs[cur];
        const float* dc = ds[cur];

        float sva[8], svb[8];
        float smaxa = -1e30f, smaxb = -1e30f;
        #pragma unroll
        for (int kk = 0; kk < 8; kk++) {
            const ulonglong2* kp = (const ulonglong2*)(Kc + kk * 256 + (h << 5));
            unsigned long long accA = 0ull, accB = 0ull, accC = 0ull, accD = 0ull;
            #pragma unroll
            for (int d4 = 0; d4 < 8; d4++) {
                ulonglong2 k2 = kp[d4];
                accA = fma2(qa[2*d4],   k2.x, accA);
                accB = fma2(qa[2*d4+1], k2.y, accB);
                accC = fma2(qb[2*d4],   k2.x, accC);
                accD = fma2(qb[2*d4+1], k2.y, accD);
            }
            float2 fa = unpack2(accA), fb = unpack2(accB);
            float2 fc = unpack2(accC), fd = unpack2(accD);
            float sA = ((fa.x + fa.y) + (fb.x + fb.y)) * scale + dc[kk * 64 + q];
            float sB = ((fc.x + fc.y) + (fd.x + fd.y)) * scale + dc[kk * 64 + 32 + q];
            sva[kk] = sA; svb[kk] = sB;
            smaxa = fmaxf(smaxa, sA);
            smaxb = fmaxf(smaxb, sB);
        }
        float mna = fmaxf(ma, smaxa);
        if (__any_sync(0xFFFFFFFFu, mna > ma)) {
            float corr = __expf(ma - mna);
            la *= corr;
            unsigned long long cc = pack2(corr, corr);
            #pragma unroll
            for (int d = 0; d < 16; d++) oa[d] = mul2(oa[d], cc);
            ma = mna;
        }
        float mnb = fmaxf(mb, smaxb);
        if (__any_sync(0xFFFFFFFFu, mnb > mb)) {
            float corr = __expf(mb - mnb);
            lb *= corr;
            unsigned long long cc = pack2(corr, corr);
            #pragma unroll
            for (int d = 0; d < 16; d++) ob[d] = mul2(ob[d], cc);
            mb = mnb;
        }
        #pragma unroll
        for (int kk = 0; kk < 8; kk++) {
            float pA = __expf(sva[kk] - ma);
            float pB = __expf(svb[kk] - mb);
            la += pA; lb += pB;
            unsigned long long p2a = pack2(pA, pA);
            unsigned long long p2b = pack2(pB, pB);
            const ulonglong2* vp = (const ulonglong2*)(Vc + kk * 256 + (h << 5));
            #pragma unroll
            for (int d4 = 0; d4 < 8; d4++) {
                ulonglong2 v2 = vp[d4];
                oa[2*d4]   = fma2(v2.x, p2a, oa[2*d4]);
                oa[2*d4+1] = fma2(v2.y, p2a, oa[2*d4+1]);
                ob[2*d4]   = fma2(v2.x, p2b, ob[2*d4]);
                ob[2*d4+1] = fma2(v2.y, p2b, ob[2*d4+1]);
            }
        }

        if (kt < 127) {
            const int nxt = cur ^ 1;
            ds[nxt][dcol * 64 + drow]       = pd.x;
            ds[nxt][(dcol + 1) * 64 + drow] = pd.y;
            cp_wait0();
        }
        __syncthreads();
    }

    float inva = 1.f / la, invb = 1.f / lb;
    float* op0 = g_AO + ((long)(b * NN + qbase + q)) * HIDD + (h << 5);
    float* op1 = g_AO + ((long)(b * NN + qbase + q + 32)) * HIDD + (h << 5);
    #pragma unroll
    for (int d4 = 0; d4 < 8; d4++) {
        float2 a0 = unpack2(oa[2*d4]), a1 = unpack2(oa[2*d4+1]);
        float2 b0 = unpack2(ob[2*d4]), b1 = unpack2(ob[2*d4+1]);
        ((float4*)op0)[d4] = make_float4(a0.x * inva, a0.y * inva, a1.x * inva, a1.y * inva);
        ((float4*)op1)[d4] = make_float4(b0.x * invb, b0.y * invb, b1.x * invb, b1.y * invb);
    }
}

// ============================================================
// Node scores: s = tanh((x . w) / ||w||). One warp per node.
// ============================================================
__global__ __launch_bounds__(256) void score_kernel(const float* __restrict__ w)
{
    int warp = (blockIdx.x * blockDim.x + threadIdx.x) >> 5;
    int lane = threadIdx.x & 31;
    if (warp >= BB * NN) return;
    const float* x = g_ENC + (long)warp * HIDD;
    float sx = 0.f, sw = 0.f;
    #pragma unroll
    for (int i = lane; i < HIDD; i += 32) {
        float wv = w[i];
        sx += x[i] * wv;
        sw += wv * wv;
    }
    #pragma unroll
    for (int off = 16; off; off >>= 1) {
        sx += __shfl_xor_sync(0xFFFFFFFFu, sx, off);
        sw += __shfl_xor_sync(0xFFFFFFFFu, sw, off);
    }
    if (lane == 0) g_score[warp] = tanhf(sx / sqrtf(sw));
}

// ============================================================
// Top-K per graph: bitonic sort of 1024 (desc score, asc index).
// ============================================================
__global__ __launch_bounds__(1024) void topk_kernel(float* __restrict__ out_perm)
{
    __shared__ unsigned long long s[NN];
    const int b = blockIdx.x, t = threadIdx.x;
    float sc = g_score[b * NN + t];
    unsigned u = __float_as_uint(sc);
    u = (u & 0x80000000u) ? ~u : (u | 0x80000000u);
    u = ~u;                                            // descending
    s[t] = (((unsigned long long)u) << 32) | (unsigned)t;
    g_nodemap[b * NN + t] = -1;
    __syncthreads();
    for (unsigned k = 2; k <= NN; k <<= 1)
        for (unsigned j = k >> 1; j; j >>= 1) {
            unsigned i = t, ixj = i ^ j;
            if (ixj > i) {
                bool up = ((i & k) == 0);
                unsigned long long a = s[i], c = s[ixj];
                if ((a > c) == up) { s[i] = c; s[ixj] = a; }
            }
            __syncthreads();
        }
    if (t < KKP) {
        int node = (int)(s[t] & 0xFFFFFFFFu);
        g_perm[b * KKP + t] = node;
        g_vals[b * KKP + t] = g_score[b * NN + node];
        out_perm[b * KKP + t] = (float)node;
        g_nodemap[b * NN + node] = t;
    }
}

// ============================================================
// sub_x gather
// ============================================================
__global__ __launch_bounds__(256) void subx_kernel(float* __restrict__ out)
{
    const int row = blockIdx.x;
    const int b = row / KKP;
    const int node = g_perm[row];
    const float val = g_vals[row];
    const float* src = g_ENC + ((long)b * NN + node) * HIDD;
    out[(long)row * HIDD + threadIdx.x] = src[threadIdx.x] * val;
}

// ============================================================
// Edge pipeline (5 kernels): build+segsort, gmerge(8192),
// smerge(8192), quadmerge(16384 j=8192+4096), smerge+emit.
// ============================================================
__global__ __launch_bounds__(1024) void edge_sortbuild(const void* __restrict__ eiraw)
{
    __shared__ unsigned long long sh[4096];
    __shared__ int s_is64;
    const int b = blockIdx.x >> 2, seg = blockIdx.x & 3;
    const int t = threadIdx.x;
    if (t == 0) {
        const unsigned* w32 = (const unsigned*)eiraw;
        int all0 = 1;
        for (int i = 0; i < 64; i++)
            if (w32[2 * i + 1] != 0u) { all0 = 0; break; }
        s_is64 = all0;
    }
    __syncthreads();
    const int is64 = s_is64;
    const int total = BB * EPER;

    #pragma unroll
    for (int li = 0; li < 4; li++) {
        int i = t + li * 1024;
        int idx = b * EPER + seg * 4096 + i;
        long long vs, vd;
        if (is64) {
            const long long* ei = (const long long*)eiraw;
            vs = ei[idx];
            vd = ei[total + idx];
        } else {
            const int* ei = (const int*)eiraw;
            vs = ei[idx];
            vd = ei[total + idx];
        }
        int src = (int)(vs - (long long)b * NN);
        int dst = (int)(vd - (long long)b * NN);
        src = min(max(src, 0), NN - 1);
        dst = min(max(dst, 0), NN - 1);
        int nu = g_nodemap[b * NN + src];
        int nv = g_nodemap[b * NN + dst];
        bool valid = (nu >= 0) && (nv >= 0);
        unsigned key = valid ? (unsigned)(nu * KKP + nv) : (unsigned)(KKP * KKP);
        int ou = valid ? nu : -1, ov = valid ? nv : -1;
        sh[i] = (((unsigned long long)key) << 21)
              | (((unsigned long long)(ou + 1)) << 11)
              | (((unsigned long long)(ov + 1)) << 1)
              | (valid ? 1ull : 0ull);
    }
    __syncthreads();

    for (unsigned k = 2; k <= 4096; k <<= 1)
        for (unsigned j = k >> 1; j; j >>= 1) {
            for (int loc = t; loc < 4096; loc += 1024) {
                unsigned i2 = (unsigned)loc, ixj = i2 ^ j;
                if (ixj > i2) {
                    unsigned gi = seg * 4096 + i2;
                    bool up = ((gi & k) == 0);
                    unsigned long long a = sh[i2], c = sh[ixj];
                    if ((a > c) == up) { sh[i2] = c; sh[ixj] = a; }
                }
            }
            __syncthreads();
        }
    unsigned long long* es = g_es + (long)b * EPER + seg * 4096;
    for (int i = t; i < 4096; i += 1024) es[i] = sh[i];
}

__global__ __launch_bounds__(1024) void edge_gmerge(unsigned k, unsigned j)
{
    int loc = blockIdx.x * blockDim.x + threadIdx.x;
    unsigned i = (unsigned)(loc & (EPER - 1));
    int b = loc >> 14;
    unsigned ixj = i ^ j;
    if (ixj > i) {
        unsigned long long* es = g_es + (long)b * EPER;
        bool up = ((i & k) == 0);
        unsigned long long a = es[i], c = es[ixj];
        if ((a > c) == up) { es[i] = c; es[ixj] = a; }
    }
}

// k=16384 steps j=8192 and j=4096 fused (all directions ascending).
__global__ __launch_bounds__(1024) void edge_quadmerge()
{
    const int b = blockIdx.x >> 2, seg = blockIdx.x & 3;
    const int i0 = seg * 1024 + threadIdx.x;
    unsigned long long* es = g_es + (long)b * EPER;
    unsigned long long v0 = es[i0];
    unsigned long long v1 = es[i0 + 4096];
    unsigned long long v2 = es[i0 + 8192];
    unsigned long long v3 = es[i0 + 12288];
    unsigned long long w;
    if (v0 > v2) { w = v0; v0 = v2; v2 = w; }   // j = 8192
    if (v1 > v3) { w = v1; v1 = v3; v3 = w; }
    if (v0 > v1) { w = v0; v0 = v1; v1 = w; }   // j = 4096
    if (v2 > v3) { w = v2; v2 = v3; v3 = w; }
    es[i0]         = v0;
    es[i0 + 4096]  = v1;
    es[i0 + 8192]  = v2;
    es[i0 + 12288] = v3;
}

__global__ __launch_bounds__(1024) void edge_smerge(unsigned k)
{
    __shared__ unsigned long long sh[4096];
    const int b = blockIdx.x >> 2, seg = blockIdx.x & 3;
    const int t = threadIdx.x;
    unsigned long long* es = g_es + (long)b * EPER + seg * 4096;
    for (int i = t; i < 4096; i += 1024) sh[i] = es[i];
    __syncthreads();
    for (unsigned j = 2048; j; j >>= 1) {
        for (int loc = t; loc < 4096; loc += 1024) {
            unsigned i2 = (unsigned)loc, ixj = i2 ^ j;
            if (ixj > i2) {
                unsigned gi = seg * 4096 + i2;
                bool up = ((gi & k) == 0);
                unsigned long long a = sh[i2], c = sh[ixj];
                if ((a > c) == up) { sh[i2] = c; sh[ixj] = a; }
            }
        }
        __syncthreads();
    }
    for (int i = t; i < 4096; i += 1024) es[i] = sh[i];
}

// Final merge tail (k = 16384, j = 2048..1) fused with emit.
__global__ __launch_bounds__(1024) void edge_smerge_emit(
    float* __restrict__ out_e, float* __restrict__ out_valid)
{
    __shared__ unsigned long long sh[4096];
    const int b = blockIdx.x >> 2, seg = blockIdx.x & 3;
    const int t = threadIdx.x;
    const unsigned k = 16384u;
    unsigned long long* es = g_es + (long)b * EPER + seg * 4096;
    for (int i = t; i < 4096; i += 1024) sh[i] = es[i];
    __syncthreads();
    for (unsigned j = 2048; j; j >>= 1) {
        for (int loc = t; loc < 4096; loc += 1024) {
            unsigned i2 = (unsigned)loc, ixj = i2 ^ j;
            if (ixj > i2) {
                unsigned gi = seg * 4096 + i2;
                bool up = ((gi & k) == 0);
                unsigned long long a = sh[i2], c = sh[ixj];
                if ((a > c) == up) { sh[i2] = c; sh[ixj] = a; }
            }
        }
        __syncthreads();
    }
    for (int i = t; i < 4096; i += 1024) {
        unsigned long long p = sh[i];
        int e = seg * 4096 + i;
        int ou = (int)((p >> 11) & 0x3FFu) - 1;
        int ov = (int)((p >> 1) & 0x3FFu) - 1;
        out_e[(long)b * 2 * EPER + e]        = (float)ou;
        out_e[(long)b * 2 * EPER + EPER + e] = (float)ov;
        out_valid[(long)b * EPER + e]        = (float)(p & 1ull);
    }
}

// ============================================================
extern "C" void kernel_launch(void* const* d_in, const int* in_sizes, int n_in,
                              void* d_out, int out_size)
{
    const float* X    = (const float*)d_in[0];
    const void*  EI   = d_in[1];
    const float* DIST = (const float*)d_in[3];
    const float* Wq   = (const float*)d_in[5];
    const float* Wk   = (const float*)d_in[6];
    const float* Wv   = (const float*)d_in[7];
    const float* Wo   = (const float*)d_in[8];
    const float* tw   = (const float*)d_in[9];
    float* out = (float*)d_out;

    gemm_k<<<dim3(4, 64, 3), 256>>>(X, Wq, Wk, Wv, 0, out + OFF_ENC);

    attn_kernel<<<dim3(16, 8), 256>>>(DIST);

    gemm_k<<<dim3(4, 64, 1), 256>>>(X, Wo, Wo, Wo, 3, out + OFF_ENC);

    score_kernel<<<(BB * NN * 32) / 256, 256>>>(tw);
    topk_kernel<<<BB, NN>>>(out + OFF_PERM);
    subx_kernel<<<BB * KKP, 256>>>(out + OFF_SUBX);

    edge_sortbuild<<<32, 1024>>>(EI);
    edge_gmerge<<<128, 1024>>>(8192u, 4096u);
    edge_smerge<<<32, 1024>>>(8192u);
    edge_quadmerge<<<32, 1024>>>();
    edge_smerge_emit<<<32, 1024>>>(out + OFF_EDGE, out + OFF_VALID);
}

// round 15
// speedup vs baseline: 1.0775x; 1.0122x over previous
#include <cuda_runtime.h>

#define BB 8
#define NN 1024
#define HIDD 256
#define HEADS 8
#define DHH 32
#define EPER 16384
#define KKP 512

// ---- output layout (float32, concatenated flattened outputs) ----
#define OFF_ENC   0
#define OFF_SUBX  (BB*NN*HIDD)
#define OFF_EDGE  (OFF_SUBX + BB*KKP*HIDD)
#define OFF_PERM  (OFF_EDGE + BB*2*EPER)
#define OFF_VALID (OFF_PERM + BB*KKP)

// ---- device scratch ----
__device__ float g_Q[BB*NN*HIDD];
__device__ float g_K[BB*NN*HIDD];
__device__ float g_V[BB*NN*HIDD];
__device__ float g_AO[BB*NN*HIDD];
__device__ float g_score[BB*NN];
__device__ int   g_perm[BB*KKP];
__device__ float g_vals[BB*KKP];
__device__ int   g_nodemap[BB*NN];
__device__ unsigned long long g_es[BB*EPER];

// ---- packed f32x2 helpers ----
__device__ __forceinline__ unsigned long long fma2(
    unsigned long long a, unsigned long long b, unsigned long long c) {
    unsigned long long d;
    asm("fma.rn.f32x2 %0, %1, %2, %3;" : "=l"(d) : "l"(a), "l"(b), "l"(c));
    return d;
}
__device__ __forceinline__ unsigned long long mul2(
    unsigned long long a, unsigned long long b) {
    unsigned long long d;
    asm("mul.rn.f32x2 %0, %1, %2;" : "=l"(d) : "l"(a), "l"(b));
    return d;
}
__device__ __forceinline__ unsigned long long pack2(float lo, float hi) {
    unsigned long long r;
    asm("mov.b64 %0, {%1, %2};" : "=l"(r) : "f"(lo), "f"(hi));
    return r;
}
__device__ __forceinline__ float2 unpack2(unsigned long long v) {
    float2 r;
    asm("mov.b64 {%0, %1}, %2;" : "=f"(r.x), "=f"(r.y) : "l"(v));
    return r;
}
__device__ __forceinline__ void cp16(unsigned smem, const void* g) {
    asm volatile("cp.async.cg.shared.global [%0], [%1], 16;" :: "r"(smem), "l"(g));
}
__device__ __forceinline__ void cp_commit() {
    asm volatile("cp.async.commit_group;");
}
__device__ __forceinline__ void cp_wait0() {
    asm volatile("cp.async.wait_group 0;");
}

// ============================================================
// Fused QKV GEMM: {Q,K,V}[8192,256] = X[8192,256] @ {Wq,Wk,Wv}
// One A staging shared by 3 accumulator sets. Per-element fma
// chain identical to champion gemm (numerics frozen).
// ============================================================
__global__ __launch_bounds__(256) void gemm_qkv(
    const float* __restrict__ X, const float* __restrict__ Wq,
    const float* __restrict__ Wk, const float* __restrict__ Wv)
{
    __shared__ float As[16][128];        // 8KB
    __shared__ float Ws[3][16][64];      // 12KB
    const int t  = threadIdx.x;
    const int tx = t & 15;
    const int ty = t >> 4;
    const int rowBase = blockIdx.y * 128;
    const int colBase = blockIdx.x * 64;

    unsigned long long aQ[8][2], aK[8][2], aV[8][2];
    #pragma unroll
    for (int i = 0; i < 8; i++) {
        aQ[i][0] = 0ull; aQ[i][1] = 0ull;
        aK[i][0] = 0ull; aK[i][1] = 0ull;
        aV[i][0] = 0ull; aV[i][1] = 0ull;
    }

    const int wr = t >> 4, wc = (t & 15) << 2;

    for (int k0 = 0; k0 < 256; k0 += 16) {
        #pragma unroll
        for (int li = 0; li < 2; li++) {
            int idx = t * 2 + li;
            int row = idx >> 2;
            int c4  = (idx & 3) << 2;
            float4 a4 = *(const float4*)(X + (rowBase + row) * 256 + k0 + c4);
            As[c4 + 0][row] = a4.x; As[c4 + 1][row] = a4.y;
            As[c4 + 2][row] = a4.z; As[c4 + 3][row] = a4.w;
        }
        *(float4*)(&Ws[0][wr][wc]) = *(const float4*)(Wq + (k0 + wr) * 256 + colBase + wc);
        *(float4*)(&Ws[1][wr][wc]) = *(const float4*)(Wk + (k0 + wr) * 256 + colBase + wc);
        *(float4*)(&Ws[2][wr][wc]) = *(const float4*)(Wv + (k0 + wr) * 256 + colBase + wc);
        __syncthreads();
        #pragma unroll
        for (int kk = 0; kk < 16; kk++) {
            float4 a0 = *(const float4*)(&As[kk][ty << 3]);
            float4 a1 = *(const float4*)(&As[kk][(ty << 3) + 4]);
            unsigned long long b0 = pack2(a0.x, a0.x), b1 = pack2(a0.y, a0.y);
            unsigned long long b2 = pack2(a0.z, a0.z), b3 = pack2(a0.w, a0.w);
            unsigned long long b4 = pack2(a1.x, a1.x), b5 = pack2(a1.y, a1.y);
            unsigned long long b6 = pack2(a1.z, a1.z), b7 = pack2(a1.w, a1.w);
            {
                ulonglong2 w2 = *(const ulonglong2*)(&Ws[0][kk][tx << 2]);
                aQ[0][0] = fma2(b0, w2.x, aQ[0][0]); aQ[0][1] = fma2(b0, w2.y, aQ[0][1]);
                aQ[1][0] = fma2(b1, w2.x, aQ[1][0]); aQ[1][1] = fma2(b1, w2.y, aQ[1][1]);
                aQ[2][0] = fma2(b2, w2.x, aQ[2][0]); aQ[2][1] = fma2(b2, w2.y, aQ[2][1]);
                aQ[3][0] = fma2(b3, w2.x, aQ[3][0]); aQ[3][1] = fma2(b3, w2.y, aQ[3][1]);
                aQ[4][0] = fma2(b4, w2.x, aQ[4][0]); aQ[4][1] = fma2(b4, w2.y, aQ[4][1]);
                aQ[5][0] = fma2(b5, w2.x, aQ[5][0]); aQ[5][1] = fma2(b5, w2.y, aQ[5][1]);
                aQ[6][0] = fma2(b6, w2.x, aQ[6][0]); aQ[6][1] = fma2(b6, w2.y, aQ[6][1]);
                aQ[7][0] = fma2(b7, w2.x, aQ[7][0]); aQ[7][1] = fma2(b7, w2.y, aQ[7][1]);
            }
            {
                ulonglong2 w2 = *(const ulonglong2*)(&Ws[1][kk][tx << 2]);
                aK[0][0] = fma2(b0, w2.x, aK[0][0]); aK[0][1] = fma2(b0, w2.y, aK[0][1]);
                aK[1][0] = fma2(b1, w2.x, aK[1][0]); aK[1][1] = fma2(b1, w2.y, aK[1][1]);
                aK[2][0] = fma2(b2, w2.x, aK[2][0]); aK[2][1] = fma2(b2, w2.y, aK[2][1]);
                aK[3][0] = fma2(b3, w2.x, aK[3][0]); aK[3][1] = fma2(b3, w2.y, aK[3][1]);
                aK[4][0] = fma2(b4, w2.x, aK[4][0]); aK[4][1] = fma2(b4, w2.y, aK[4][1]);
                aK[5][0] = fma2(b5, w2.x, aK[5][0]); aK[5][1] = fma2(b5, w2.y, aK[5][1]);
                aK[6][0] = fma2(b6, w2.x, aK[6][0]); aK[6][1] = fma2(b6, w2.y, aK[6][1]);
                aK[7][0] = fma2(b7, w2.x, aK[7][0]); aK[7][1] = fma2(b7, w2.y, aK[7][1]);
            }
            {
                ulonglong2 w2 = *(const ulonglong2*)(&Ws[2][kk][tx << 2]);
                aV[0][0] = fma2(b0, w2.x, aV[0][0]); aV[0][1] = fma2(b0, w2.y, aV[0][1]);
                aV[1][0] = fma2(b1, w2.x, aV[1][0]); aV[1][1] = fma2(b1, w2.y, aV[1][1]);
                aV[2][0] = fma2(b2, w2.x, aV[2][0]); aV[2][1] = fma2(b2, w2.y, aV[2][1]);
                aV[3][0] = fma2(b3, w2.x, aV[3][0]); aV[3][1] = fma2(b3, w2.y, aV[3][1]);
                aV[4][0] = fma2(b4, w2.x, aV[4][0]); aV[4][1] = fma2(b4, w2.y, aV[4][1]);
                aV[5][0] = fma2(b5, w2.x, aV[5][0]); aV[5][1] = fma2(b5, w2.y, aV[5][1]);
                aV[6][0] = fma2(b6, w2.x, aV[6][0]); aV[6][1] = fma2(b6, w2.y, aV[6][1]);
                aV[7][0] = fma2(b7, w2.x, aV[7][0]); aV[7][1] = fma2(b7, w2.y, aV[7][1]);
            }
        }
        __syncthreads();
    }
    #pragma unroll
    for (int i = 0; i < 8; i++) {
        long off = (long)(rowBase + (ty << 3) + i) * 256 + colBase + (tx << 2);
        float2 lo, hi;
        lo = unpack2(aQ[i][0]); hi = unpack2(aQ[i][1]);
        *(float4*)(g_Q + off) = make_float4(lo.x, lo.y, hi.x, hi.y);
        lo = unpack2(aK[i][0]); hi = unpack2(aK[i][1]);
        *(float4*)(g_K + off) = make_float4(lo.x, lo.y, hi.x, hi.y);
        lo = unpack2(aV[i][0]); hi = unpack2(aV[i][1]);
        *(float4*)(g_V + off) = make_float4(lo.x, lo.y, hi.x, hi.y);
    }
}

// ============================================================
// Output GEMM: enc = g_AO @ Wo, written ONLY to out (champion
// inner loop verbatim; numerics frozen).
// ============================================================
__global__ __launch_bounds__(256) void gemm_o(
    const float* __restrict__ Wo, float* __restrict__ outEnc)
{
    const float* A = g_AO;
    __shared__ float As[16][128];
    __shared__ float Ws[16][64];
    const int t  = threadIdx.x;
    const int tx = t & 15;
    const int ty = t >> 4;
    const int rowBase = blockIdx.y * 128;
    const int colBase = blockIdx.x * 64;

    unsigned long long acc2[8][2];
    #pragma unroll
    for (int i = 0; i < 8; i++) { acc2[i][0] = 0ull; acc2[i][1] = 0ull; }

    const int wr = t >> 4, wc = (t & 15) << 2;

    for (int k0 = 0; k0 < 256; k0 += 16) {
        #pragma unroll
        for (int li = 0; li < 2; li++) {
            int idx = t * 2 + li;
            int row = idx >> 2;
            int c4  = (idx & 3) << 2;
            float4 a4 = *(const float4*)(A + (rowBase + row) * 256 + k0 + c4);
            As[c4 + 0][row] = a4.x; As[c4 + 1][row] = a4.y;
            As[c4 + 2][row] = a4.z; As[c4 + 3][row] = a4.w;
        }
        *(float4*)(&Ws[wr][wc]) = *(const float4*)(Wo + (k0 + wr) * 256 + colBase + wc);
        __syncthreads();
        #pragma unroll
        for (int kk = 0; kk < 16; kk++) {
            float4 a0 = *(const float4*)(&As[kk][ty << 3]);
            float4 a1 = *(const float4*)(&As[kk][(ty << 3) + 4]);
            ulonglong2 w2 = *(const ulonglong2*)(&Ws[kk][tx << 2]);
            unsigned long long b0 = pack2(a0.x, a0.x), b1 = pack2(a0.y, a0.y);
            unsigned long long b2 = pack2(a0.z, a0.z), b3 = pack2(a0.w, a0.w);
            unsigned long long b4 = pack2(a1.x, a1.x), b5 = pack2(a1.y, a1.y);
            unsigned long long b6 = pack2(a1.z, a1.z), b7 = pack2(a1.w, a1.w);
            acc2[0][0] = fma2(b0, w2.x, acc2[0][0]); acc2[0][1] = fma2(b0, w2.y, acc2[0][1]);
            acc2[1][0] = fma2(b1, w2.x, acc2[1][0]); acc2[1][1] = fma2(b1, w2.y, acc2[1][1]);
            acc2[2][0] = fma2(b2, w2.x, acc2[2][0]); acc2[2][1] = fma2(b2, w2.y, acc2[2][1]);
            acc2[3][0] = fma2(b3, w2.x, acc2[3][0]); acc2[3][1] = fma2(b3, w2.y, acc2[3][1]);
            acc2[4][0] = fma2(b4, w2.x, acc2[4][0]); acc2[4][1] = fma2(b4, w2.y, acc2[4][1]);
            acc2[5][0] = fma2(b5, w2.x, acc2[5][0]); acc2[5][1] = fma2(b5, w2.y, acc2[5][1]);
            acc2[6][0] = fma2(b6, w2.x, acc2[6][0]); acc2[6][1] = fma2(b6, w2.y, acc2[6][1]);
            acc2[7][0] = fma2(b7, w2.x, acc2[7][0]); acc2[7][1] = fma2(b7, w2.y, acc2[7][1]);
        }
        __syncthreads();
    }
    #pragma unroll
    for (int i = 0; i < 8; i++) {
        int row = rowBase + (ty << 3) + i;
        float2 lo = unpack2(acc2[i][0]), hi = unpack2(acc2[i][1]);
        *(float4*)(outEnc + (long)row * 256 + colBase + (tx << 2)) =
            make_float4(lo.x, lo.y, hi.x, hi.y);
    }
}

// ============================================================
// Attention: round-7 formulation VERBATIM (numerics frozen).
// ============================================================
__global__ __launch_bounds__(256, 1) void attn_kernel(const float* __restrict__ dist)
{
    __shared__ float Ks[2][8 * 256];
    __shared__ float Vs[2][8 * 256];
    __shared__ float ds[2][8 * 64];   // [k][q] transposed

    const int b = blockIdx.y;
    const int qbase = blockIdx.x * 64;
    const int t = threadIdx.x;
    const int h = t >> 5, q = t & 31;
    const int drow = t >> 2, dcol = (t & 3) << 1;

    const float* Kg = g_K + (long)b * NN * HIDD;
    const float* Vg = g_V + (long)b * NN * HIDD;
    const float* dg = dist + ((long)(b * NN + qbase + drow)) * NN + dcol;

    unsigned ks_base = (unsigned)__cvta_generic_to_shared(&Ks[0][0]);
    unsigned vs_base = (unsigned)__cvta_generic_to_shared(&Vs[0][0]);

    unsigned long long qa[16], qb[16];
    {
        const ulonglong2* qp0 = (const ulonglong2*)(g_Q + ((long)(b * NN + qbase + q)) * HIDD + (h << 5));
        const ulonglong2* qp1 = (const ulonglong2*)(g_Q + ((long)(b * NN + qbase + q + 32)) * HIDD + (h << 5));
        #pragma unroll
        for (int d4 = 0; d4 < 8; d4++) {
            ulonglong2 v0 = qp0[d4], v1 = qp1[d4];
            qa[2*d4] = v0.x; qa[2*d4+1] = v0.y;
            qb[2*d4] = v1.x; qb[2*d4+1] = v1.y;
        }
    }

    {
        cp16(ks_base + t * 16,             (const char*)Kg + t * 16);
        cp16(ks_base + (t + 256) * 16,     (const char*)Kg + (t + 256) * 16);
        cp16(vs_base + t * 16,             (const char*)Vg + t * 16);
        cp16(vs_base + (t + 256) * 16,     (const char*)Vg + (t + 256) * 16);
        cp_commit();
        float2 d0 = *(const float2*)dg;
        ds[0][dcol * 64 + drow]       = d0.x;
        ds[0][(dcol + 1) * 64 + drow] = d0.y;
        cp_wait0();
    }
    __syncthreads();

    float ma = -1e30f, la = 0.f, mb = -1e30f, lb = 0.f;
    unsigned long long oa[16], ob[16];
    #pragma unroll
    for (int d = 0; d < 16; d++) { oa[d] = 0ull; ob[d] = 0ull; }
    const float scale = 0.1767766952966369f;  // 1/sqrt(32)

    for (int kt = 0; kt < 128; kt++) {
        const int cur = kt & 1;
        float2 pd;
        if (kt < 127) {
            const int nxt = cur ^ 1;
            const char* Kn = (const char*)Kg + (kt + 1) * 8192;
            const char* Vn = (const char*)Vg + (kt + 1) * 8192;
            unsigned ksn = ks_base + nxt * 8192;
            unsigned vsn = vs_base + nxt * 8192;
            cp16(ksn + t * 16,         Kn + t * 16);
            cp16(ksn + (t + 256) * 16, Kn + (t + 256) * 16);
            cp16(vsn + t * 16,         Vn + t * 16);
            cp16(vsn + (t + 256) * 16, Vn + (t + 256) * 16);
            cp_commit();
            pd = *(const float2*)(dg + (kt + 1) * 8);
        }

        const float* Kc = Ks[cur];
        const float* Vc = Vs[cur];
        const float* dc = ds[cur];

        float sva[8], svb[8];
        float smaxa = -1e30f, smaxb = -1e30f;
        #pragma unroll
        for (int kk = 0; kk < 8; kk++) {
            const ulonglong2* kp = (const ulonglong2*)(Kc + kk * 256 + (h << 5));
            unsigned long long accA = 0ull, accB = 0ull, accC = 0ull, accD = 0ull;
            #pragma unroll
            for (int d4 = 0; d4 < 8; d4++) {
                ulonglong2 k2 = kp[d4];
                accA = fma2(qa[2*d4],   k2.x, accA);
                accB = fma2(qa[2*d4+1], k2.y, accB);
                accC = fma2(qb[2*d4],   k2.x, accC);
                accD = fma2(qb[2*d4+1], k2.y, accD);
            }
            float2 fa = unpack2(accA), fb = unpack2(accB);
            float2 fc = unpack2(accC), fd = unpack2(accD);
            float sA = ((fa.x + fa.y) + (fb.x + fb.y)) * scale + dc[kk * 64 + q];
            float sB = ((fc.x + fc.y) + (fd.x + fd.y)) * scale + dc[kk * 64 + 32 + q];
            sva[kk] = sA; svb[kk] = sB;
            smaxa = fmaxf(smaxa, sA);
            smaxb = fmaxf(smaxb, sB);
        }
        float mna = fmaxf(ma, smaxa);
        if (__any_sync(0xFFFFFFFFu, mna > ma)) {
            float corr = __expf(ma - mna);
            la *= corr;
            unsigned long long cc = pack2(corr, corr);
            #pragma unroll
            for (int d = 0; d < 16; d++) oa[d] = mul2(oa[d], cc);
            ma = mna;
        }
        float mnb = fmaxf(mb, smaxb);
        if (__any_sync(0xFFFFFFFFu, mnb > mb)) {
            float corr = __expf(mb - mnb);
            lb *= corr;
            unsigned long long cc = pack2(corr, corr);
            #pragma unroll
            for (int d = 0; d < 16; d++) ob[d] = mul2(ob[d], cc);
            mb = mnb;
        }
        #pragma unroll
        for (int kk = 0; kk < 8; kk++) {
            float pA = __expf(sva[kk] - ma);
            float pB = __expf(svb[kk] - mb);
            la += pA; lb += pB;
            unsigned long long p2a = pack2(pA, pA);
            unsigned long long p2b = pack2(pB, pB);
            const ulonglong2* vp = (const ulonglong2*)(Vc + kk * 256 + (h << 5));
            #pragma unroll
            for (int d4 = 0; d4 < 8; d4++) {
                ulonglong2 v2 = vp[d4];
                oa[2*d4]   = fma2(v2.x, p2a, oa[2*d4]);
                oa[2*d4+1] = fma2(v2.y, p2a, oa[2*d4+1]);
                ob[2*d4]   = fma2(v2.x, p2b, ob[2*d4]);
                ob[2*d4+1] = fma2(v2.y, p2b, ob[2*d4+1]);
            }
        }

        if (kt < 127) {
            const int nxt = cur ^ 1;
            ds[nxt][dcol * 64 + drow]       = pd.x;
            ds[nxt][(dcol + 1) * 64 + drow] = pd.y;
            cp_wait0();
        }
        __syncthreads();
    }

    float inva = 1.f / la, invb = 1.f / lb;
    float* op0 = g_AO + ((long)(b * NN + qbase + q)) * HIDD + (h << 5);
    float* op1 = g_AO + ((long)(b * NN + qbase + q + 32)) * HIDD + (h << 5);
    #pragma unroll
    for (int d4 = 0; d4 < 8; d4++) {
        float2 a0 = unpack2(oa[2*d4]), a1 = unpack2(oa[2*d4+1]);
        float2 b0 = unpack2(ob[2*d4]), b1 = unpack2(ob[2*d4+1]);
        ((float4*)op0)[d4] = make_float4(a0.x * inva, a0.y * inva, a1.x * inva, a1.y * inva);
        ((float4*)op1)[d4] = make_float4(b0.x * invb, b0.y * invb, b1.x * invb, b1.y * invb);
    }
}

// ============================================================
// Node scores from out[OFF_ENC]: s = tanh((x . w) / ||w||).
// ============================================================
__global__ __launch_bounds__(256) void score_kernel(
    const float* __restrict__ enc, const float* __restrict__ w)
{
    int warp = (blockIdx.x * blockDim.x + threadIdx.x) >> 5;
    int lane = threadIdx.x & 31;
    if (warp >= BB * NN) return;
    const float* x = enc + (long)warp * HIDD;
    float sx = 0.f, sw = 0.f;
    #pragma unroll
    for (int i = lane; i < HIDD; i += 32) {
        float wv = w[i];
        sx += x[i] * wv;
        sw += wv * wv;
    }
    #pragma unroll
    for (int off = 16; off; off >>= 1) {
        sx += __shfl_xor_sync(0xFFFFFFFFu, sx, off);
        sw += __shfl_xor_sync(0xFFFFFFFFu, sw, off);
    }
    if (lane == 0) g_score[warp] = tanhf(sx / sqrtf(sw));
}

// ============================================================
// Top-K per graph: bitonic sort of 1024 (desc score, asc index).
// ============================================================
__global__ __launch_bounds__(1024) void topk_kernel(float* __restrict__ out_perm)
{
    __shared__ unsigned long long s[NN];
    const int b = blockIdx.x, t = threadIdx.x;
    float sc = g_score[b * NN + t];
    unsigned u = __float_as_uint(sc);
    u = (u & 0x80000000u) ? ~u : (u | 0x80000000u);
    u = ~u;                                            // descending
    s[t] = (((unsigned long long)u) << 32) | (unsigned)t;
    g_nodemap[b * NN + t] = -1;
    __syncthreads();
    for (unsigned k = 2; k <= NN; k <<= 1)
        for (unsigned j = k >> 1; j; j >>= 1) {
            unsigned i = t, ixj = i ^ j;
            if (ixj > i) {
                bool up = ((i & k) == 0);
                unsigned long long a = s[i], c = s[ixj];
                if ((a > c) == up) { s[i] = c; s[ixj] = a; }
            }
            __syncthreads();
        }
    if (t < KKP) {
        int node = (int)(s[t] & 0xFFFFFFFFu);
        g_perm[b * KKP + t] = node;
        g_vals[b * KKP + t] = g_score[b * NN + node];
        out_perm[b * KKP + t] = (float)node;
        g_nodemap[b * NN + node] = t;
    }
}

// ============================================================
// sub_x gather: 4 rows per block, reads enc from out[OFF_ENC].
// ============================================================
__global__ __launch_bounds__(256) void subx_kernel(
    const float* __restrict__ enc, float* __restrict__ out)
{
    const int row0 = blockIdx.x * 4;
    #pragma unroll
    for (int r = 0; r < 4; r++) {
        int row = row0 + r;
        int b = row / KKP;
        int node = g_perm[row];
        float val = g_vals[row];
        const float* src = enc + ((long)b * NN + node) * HIDD;
        out[(long)row * HIDD + threadIdx.x] = src[threadIdx.x] * val;
    }
}

// ============================================================
// Edge pipeline (5 kernels, round-14 verbatim).
// ============================================================
__global__ __launch_bounds__(1024) void edge_sortbuild(const void* __restrict__ eiraw)
{
    __shared__ unsigned long long sh[4096];
    __shared__ int s_is64;
    const int b = blockIdx.x >> 2, seg = blockIdx.x & 3;
    const int t = threadIdx.x;
    if (t == 0) {
        const unsigned* w32 = (const unsigned*)eiraw;
        int all0 = 1;
        for (int i = 0; i < 64; i++)
            if (w32[2 * i + 1] != 0u) { all0 = 0; break; }
        s_is64 = all0;
    }
    __syncthreads();
    const int is64 = s_is64;
    const int total = BB * EPER;

    #pragma unroll
    for (int li = 0; li < 4; li++) {
        int i = t + li * 1024;
        int idx = b * EPER + seg * 4096 + i;
        long long vs, vd;
        if (is64) {
            const long long* ei = (const long long*)eiraw;
            vs = ei[idx];
            vd = ei[total + idx];
        } else {
            const int* ei = (const int*)eiraw;
            vs = ei[idx];
            vd = ei[total + idx];
        }
        int src = (int)(vs - (long long)b * NN);
        int dst = (int)(vd - (long long)b * NN);
        src = min(max(src, 0), NN - 1);
        dst = min(max(dst, 0), NN - 1);
        int nu = g_nodemap[b * NN + src];
        int nv = g_nodemap[b * NN + dst];
        bool valid = (nu >= 0) && (nv >= 0);
        unsigned key = valid ? (unsigned)(nu * KKP + nv) : (unsigned)(KKP * KKP);
        int ou = valid ? nu : -1, ov = valid ? nv : -1;
        sh[i] = (((unsigned long long)key) << 21)
              | (((unsigned long long)(ou + 1)) << 11)
              | (((unsigned long long)(ov + 1)) << 1)
              | (valid ? 1ull : 0ull);
    }
    __syncthreads();

    for (unsigned k = 2; k <= 4096; k <<= 1)
        for (unsigned j = k >> 1; j; j >>= 1) {
            for (int loc = t; loc < 4096; loc += 1024) {
                unsigned i2 = (unsigned)loc, ixj = i2 ^ j;
                if (ixj > i2) {
                    unsigned gi = seg * 4096 + i2;
                    bool up = ((gi & k) == 0);
                    unsigned long long a = sh[i2], c = sh[ixj];
                    if ((a > c) == up) { sh[i2] = c; sh[ixj] = a; }
                }
            }
            __syncthreads();
        }
    unsigned long long* es = g_es + (long)b * EPER + seg * 4096;
    for (int i = t; i < 4096; i += 1024) es[i] = sh[i];
}

__global__ __launch_bounds__(1024) void edge_gmerge(unsigned k, unsigned j)
{
    int loc = blockIdx.x * blockDim.x + threadIdx.x;
    unsigned i = (unsigned)(loc & (EPER - 1));
    int b = loc >> 14;
    unsigned ixj = i ^ j;
    if (ixj > i) {
        unsigned long long* es = g_es + (long)b * EPER;
        bool up = ((i & k) == 0);
        unsigned long long a = es[i], c = es[ixj];
        if ((a > c) == up) { es[i] = c; es[ixj] = a; }
    }
}

__global__ __launch_bounds__(1024) void edge_quadmerge()
{
    const int b = blockIdx.x >> 2, seg = blockIdx.x & 3;
    const int i0 = seg * 1024 + threadIdx.x;
    unsigned long long* es = g_es + (long)b * EPER;
    unsigned long long v0 = es[i0];
    unsigned long long v1 = es[i0 + 4096];
    unsigned long long v2 = es[i0 + 8192];
    unsigned long long v3 = es[i0 + 12288];
    unsigned long long w;
    if (v0 > v2) { w = v0; v0 = v2; v2 = w; }   // j = 8192
    if (v1 > v3) { w = v1; v1 = v3; v3 = w; }
    if (v0 > v1) { w = v0; v0 = v1; v1 = w; }   // j = 4096
    if (v2 > v3) { w = v2; v2 = v3; v3 = w; }
    es[i0]         = v0;
    es[i0 + 4096]  = v1;
    es[i0 + 8192]  = v2;
    es[i0 + 12288] = v3;
}

__global__ __launch_bounds__(1024) void edge_smerge(unsigned k)
{
    __shared__ unsigned long long sh[4096];
    const int b = blockIdx.x >> 2, seg = blockIdx.x & 3;
    const int t = threadIdx.x;
    unsigned long long* es = g_es + (long)b * EPER + seg * 4096;
    for (int i = t; i < 4096; i += 1024) sh[i] = es[i];
    __syncthreads();
    for (unsigned j = 2048; j; j >>= 1) {
        for (int loc = t; loc < 4096; loc += 1024) {
            unsigned i2 = (unsigned)loc, ixj = i2 ^ j;
            if (ixj > i2) {
                unsigned gi = seg * 4096 + i2;
                bool up = ((gi & k) == 0);
                unsigned long long a = sh[i2], c = sh[ixj];
                if ((a > c) == up) { sh[i2] = c; sh[ixj] = a; }
            }
        }
        __syncthreads();
    }
    for (int i = t; i < 4096; i += 1024) es[i] = sh[i];
}

__global__ __launch_bounds__(1024) void edge_smerge_emit(
    float* __restrict__ out_e, float* __restrict__ out_valid)
{
    __shared__ unsigned long long sh[4096];
    const int b = blockIdx.x >> 2, seg = blockIdx.x & 3;
    const int t = threadIdx.x;
    const unsigned k = 16384u;
    unsigned long long* es = g_es + (long)b * EPER + seg * 4096;
    for (int i = t; i < 4096; i += 1024) sh[i] = es[i];
    __syncthreads();
    for (unsigned j = 2048; j; j >>= 1) {
        for (int loc = t; loc < 4096; loc += 1024) {
            unsigned i2 = (unsigned)loc, ixj = i2 ^ j;
            if (ixj > i2) {
                unsigned gi = seg * 4096 + i2;
                bool up = ((gi & k) == 0);
                unsigned long long a = sh[i2], c = sh[ixj];
                if ((a > c) == up) { sh[i2] = c; sh[ixj] = a; }
            }
        }
        __syncthreads();
    }
    for (int i = t; i < 4096; i += 1024) {
        unsigned long long p = sh[i];
        int e = seg * 4096 + i;
        int ou = (int)((p >> 11) & 0x3FFu) - 1;
        int ov = (int)((p >> 1) & 0x3FFu) - 1;
        out_e[(long)b * 2 * EPER + e]        = (float)ou;
        out_e[(long)b * 2 * EPER + EPER + e] = (float)ov;
        out_valid[(long)b * EPER + e]        = (float)(p & 1ull);
    }
}

// ============================================================
extern "C" void kernel_launch(void* const* d_in, const int* in_sizes, int n_in,
                              void* d_out, int out_size)
{
    const float* X    = (const float*)d_in[0];
    const void*  EI   = d_in[1];
    const float* DIST = (const float*)d_in[3];
    const float* Wq   = (const float*)d_in[5];
    const float* Wk   = (const float*)d_in[6];
    const float* Wv   = (const float*)d_in[7];
    const float* Wo   = (const float*)d_in[8];
    const float* tw   = (const float*)d_in[9];
    float* out = (float*)d_out;

    gemm_qkv<<<dim3(4, 64), 256>>>(X, Wq, Wk, Wv);

    attn_kernel<<<dim3(16, 8), 256>>>(DIST);

    gemm_o<<<dim3(4, 64), 256>>>(Wo, out + OFF_ENC);

    score_kernel<<<(BB * NN * 32) / 256, 256>>>(out + OFF_ENC, tw);
    topk_kernel<<<BB, NN>>>(out + OFF_PERM);
    subx_kernel<<<BB * KKP / 4, 256>>>(out + OFF_ENC, out + OFF_SUBX);

    edge_sortbuild<<<32, 1024>>>(EI);
    edge_gmerge<<<128, 1024>>>(8192u, 4096u);
    edge_smerge<<<32, 1024>>>(8192u);
    edge_quadmerge<<<32, 1024>>>();
    edge_smerge_emit<<<32, 1024>>>(out + OFF_EDGE, out + OFF_VALID);
}

// round 16
// speedup vs baseline: 1.0823x; 1.0044x over previous
#include <cuda_runtime.h>

#define BB 8
#define NN 1024
#define HIDD 256
#define HEADS 8
#define DHH 32
#define EPER 16384
#define KKP 512
#define ECAP 8192

// ---- output layout (float32, concatenated flattened outputs) ----
#define OFF_ENC   0
#define OFF_SUBX  (BB*NN*HIDD)
#define OFF_EDGE  (OFF_SUBX + BB*KKP*HIDD)
#define OFF_PERM  (OFF_EDGE + BB*2*EPER)
#define OFF_VALID (OFF_PERM + BB*KKP)

// ---- device scratch ----
__device__ float g_Q[BB*NN*HIDD];
__device__ float g_K[BB*NN*HIDD];
__device__ float g_V[BB*NN*HIDD];
__device__ float g_AO[BB*NN*HIDD];
__device__ float g_score[BB*NN];
__device__ int   g_perm[BB*KKP];
__device__ float g_vals[BB*KKP];
__device__ int   g_nodemap[BB*NN];
__device__ unsigned g_ekeys[BB*ECAP];
__device__ int   g_ecount[BB];

// ---- packed f32x2 helpers ----
__device__ __forceinline__ unsigned long long fma2(
    unsigned long long a, unsigned long long b, unsigned long long c) {
    unsigned long long d;
    asm("fma.rn.f32x2 %0, %1, %2, %3;" : "=l"(d) : "l"(a), "l"(b), "l"(c));
    return d;
}
__device__ __forceinline__ unsigned long long mul2(
    unsigned long long a, unsigned long long b) {
    unsigned long long d;
    asm("mul.rn.f32x2 %0, %1, %2;" : "=l"(d) : "l"(a), "l"(b));
    return d;
}
__device__ __forceinline__ unsigned long long pack2(float lo, float hi) {
    unsigned long long r;
    asm("mov.b64 %0, {%1, %2};" : "=l"(r) : "f"(lo), "f"(hi));
    return r;
}
__device__ __forceinline__ float2 unpack2(unsigned long long v) {
    float2 r;
    asm("mov.b64 {%0, %1}, %2;" : "=f"(r.x), "=f"(r.y) : "l"(v));
    return r;
}
__device__ __forceinline__ void cp16(unsigned smem, const void* g) {
    asm volatile("cp.async.cg.shared.global [%0], [%1], 16;" :: "r"(smem), "l"(g));
}
__device__ __forceinline__ void cp_commit() {
    asm volatile("cp.async.commit_group;");
}
__device__ __forceinline__ void cp_wait0() {
    asm volatile("cp.async.wait_group 0;");
}

// ============================================================
// Fused QKV GEMM (champion verbatim; numerics frozen).
// ============================================================
__global__ __launch_bounds__(256) void gemm_qkv(
    const float* __restrict__ X, const float* __restrict__ Wq,
    const float* __restrict__ Wk, const float* __restrict__ Wv)
{
    __shared__ float As[16][128];
    __shared__ float Ws[3][16][64];
    const int t  = threadIdx.x;
    const int tx = t & 15;
    const int ty = t >> 4;
    const int rowBase = blockIdx.y * 128;
    const int colBase = blockIdx.x * 64;

    unsigned long long aQ[8][2], aK[8][2], aV[8][2];
    #pragma unroll
    for (int i = 0; i < 8; i++) {
        aQ[i][0] = 0ull; aQ[i][1] = 0ull;
        aK[i][0] = 0ull; aK[i][1] = 0ull;
        aV[i][0] = 0ull; aV[i][1] = 0ull;
    }

    const int wr = t >> 4, wc = (t & 15) << 2;

    for (int k0 = 0; k0 < 256; k0 += 16) {
        #pragma unroll
        for (int li = 0; li < 2; li++) {
            int idx = t * 2 + li;
            int row = idx >> 2;
            int c4  = (idx & 3) << 2;
            float4 a4 = *(const float4*)(X + (rowBase + row) * 256 + k0 + c4);
            As[c4 + 0][row] = a4.x; As[c4 + 1][row] = a4.y;
            As[c4 + 2][row] = a4.z; As[c4 + 3][row] = a4.w;
        }
        *(float4*)(&Ws[0][wr][wc]) = *(const float4*)(Wq + (k0 + wr) * 256 + colBase + wc);
        *(float4*)(&Ws[1][wr][wc]) = *(const float4*)(Wk + (k0 + wr) * 256 + colBase + wc);
        *(float4*)(&Ws[2][wr][wc]) = *(const float4*)(Wv + (k0 + wr) * 256 + colBase + wc);
        __syncthreads();
        #pragma unroll
        for (int kk = 0; kk < 16; kk++) {
            float4 a0 = *(const float4*)(&As[kk][ty << 3]);
            float4 a1 = *(const float4*)(&As[kk][(ty << 3) + 4]);
            unsigned long long b0 = pack2(a0.x, a0.x), b1 = pack2(a0.y, a0.y);
            unsigned long long b2 = pack2(a0.z, a0.z), b3 = pack2(a0.w, a0.w);
            unsigned long long b4 = pack2(a1.x, a1.x), b5 = pack2(a1.y, a1.y);
            unsigned long long b6 = pack2(a1.z, a1.z), b7 = pack2(a1.w, a1.w);
            {
                ulonglong2 w2 = *(const ulonglong2*)(&Ws[0][kk][tx << 2]);
                aQ[0][0] = fma2(b0, w2.x, aQ[0][0]); aQ[0][1] = fma2(b0, w2.y, aQ[0][1]);
                aQ[1][0] = fma2(b1, w2.x, aQ[1][0]); aQ[1][1] = fma2(b1, w2.y, aQ[1][1]);
                aQ[2][0] = fma2(b2, w2.x, aQ[2][0]); aQ[2][1] = fma2(b2, w2.y, aQ[2][1]);
                aQ[3][0] = fma2(b3, w2.x, aQ[3][0]); aQ[3][1] = fma2(b3, w2.y, aQ[3][1]);
                aQ[4][0] = fma2(b4, w2.x, aQ[4][0]); aQ[4][1] = fma2(b4, w2.y, aQ[4][1]);
                aQ[5][0] = fma2(b5, w2.x, aQ[5][0]); aQ[5][1] = fma2(b5, w2.y, aQ[5][1]);
                aQ[6][0] = fma2(b6, w2.x, aQ[6][0]); aQ[6][1] = fma2(b6, w2.y, aQ[6][1]);
                aQ[7][0] = fma2(b7, w2.x, aQ[7][0]); aQ[7][1] = fma2(b7, w2.y, aQ[7][1]);
            }
            {
                ulonglong2 w2 = *(const ulonglong2*)(&Ws[1][kk][tx << 2]);
                aK[0][0] = fma2(b0, w2.x, aK[0][0]); aK[0][1] = fma2(b0, w2.y, aK[0][1]);
                aK[1][0] = fma2(b1, w2.x, aK[1][0]); aK[1][1] = fma2(b1, w2.y, aK[1][1]);
                aK[2][0] = fma2(b2, w2.x, aK[2][0]); aK[2][1] = fma2(b2, w2.y, aK[2][1]);
                aK[3][0] = fma2(b3, w2.x, aK[3][0]); aK[3][1] = fma2(b3, w2.y, aK[3][1]);
                aK[4][0] = fma2(b4, w2.x, aK[4][0]); aK[4][1] = fma2(b4, w2.y, aK[4][1]);
                aK[5][0] = fma2(b5, w2.x, aK[5][0]); aK[5][1] = fma2(b5, w2.y, aK[5][1]);
                aK[6][0] = fma2(b6, w2.x, aK[6][0]); aK[6][1] = fma2(b6, w2.y, aK[6][1]);
                aK[7][0] = fma2(b7, w2.x, aK[7][0]); aK[7][1] = fma2(b7, w2.y, aK[7][1]);
            }
            {
                ulonglong2 w2 = *(const ulonglong2*)(&Ws[2][kk][tx << 2]);
                aV[0][0] = fma2(b0, w2.x, aV[0][0]); aV[0][1] = fma2(b0, w2.y, aV[0][1]);
                aV[1][0] = fma2(b1, w2.x, aV[1][0]); aV[1][1] = fma2(b1, w2.y, aV[1][1]);
                aV[2][0] = fma2(b2, w2.x, aV[2][0]); aV[2][1] = fma2(b2, w2.y, aV[2][1]);
                aV[3][0] = fma2(b3, w2.x, aV[3][0]); aV[3][1] = fma2(b3, w2.y, aV[3][1]);
                aV[4][0] = fma2(b4, w2.x, aV[4][0]); aV[4][1] = fma2(b4, w2.y, aV[4][1]);
                aV[5][0] = fma2(b5, w2.x, aV[5][0]); aV[5][1] = fma2(b5, w2.y, aV[5][1]);
                aV[6][0] = fma2(b6, w2.x, aV[6][0]); aV[6][1] = fma2(b6, w2.y, aV[6][1]);
                aV[7][0] = fma2(b7, w2.x, aV[7][0]); aV[7][1] = fma2(b7, w2.y, aV[7][1]);
            }
        }
        __syncthreads();
    }
    #pragma unroll
    for (int i = 0; i < 8; i++) {
        long off = (long)(rowBase + (ty << 3) + i) * 256 + colBase + (tx << 2);
        float2 lo, hi;
        lo = unpack2(aQ[i][0]); hi = unpack2(aQ[i][1]);
        *(float4*)(g_Q + off) = make_float4(lo.x, lo.y, hi.x, hi.y);
        lo = unpack2(aK[i][0]); hi = unpack2(aK[i][1]);
        *(float4*)(g_K + off) = make_float4(lo.x, lo.y, hi.x, hi.y);
        lo = unpack2(aV[i][0]); hi = unpack2(aV[i][1]);
        *(float4*)(g_V + off) = make_float4(lo.x, lo.y, hi.x, hi.y);
    }
}

// ============================================================
// Output GEMM: enc = g_AO @ Wo -> out only (champion verbatim).
// ============================================================
__global__ __launch_bounds__(256) void gemm_o(
    const float* __restrict__ Wo, float* __restrict__ outEnc)
{
    const float* A = g_AO;
    __shared__ float As[16][128];
    __shared__ float Ws[16][64];
    const int t  = threadIdx.x;
    const int tx = t & 15;
    const int ty = t >> 4;
    const int rowBase = blockIdx.y * 128;
    const int colBase = blockIdx.x * 64;

    unsigned long long acc2[8][2];
    #pragma unroll
    for (int i = 0; i < 8; i++) { acc2[i][0] = 0ull; acc2[i][1] = 0ull; }

    const int wr = t >> 4, wc = (t & 15) << 2;

    for (int k0 = 0; k0 < 256; k0 += 16) {
        #pragma unroll
        for (int li = 0; li < 2; li++) {
            int idx = t * 2 + li;
            int row = idx >> 2;
            int c4  = (idx & 3) << 2;
            float4 a4 = *(const float4*)(A + (rowBase + row) * 256 + k0 + c4);
            As[c4 + 0][row] = a4.x; As[c4 + 1][row] = a4.y;
            As[c4 + 2][row] = a4.z; As[c4 + 3][row] = a4.w;
        }
        *(float4*)(&Ws[wr][wc]) = *(const float4*)(Wo + (k0 + wr) * 256 + colBase + wc);
        __syncthreads();
        #pragma unroll
        for (int kk = 0; kk < 16; kk++) {
            float4 a0 = *(const float4*)(&As[kk][ty << 3]);
            float4 a1 = *(const float4*)(&As[kk][(ty << 3) + 4]);
            ulonglong2 w2 = *(const ulonglong2*)(&Ws[kk][tx << 2]);
            unsigned long long b0 = pack2(a0.x, a0.x), b1 = pack2(a0.y, a0.y);
            unsigned long long b2 = pack2(a0.z, a0.z), b3 = pack2(a0.w, a0.w);
            unsigned long long b4 = pack2(a1.x, a1.x), b5 = pack2(a1.y, a1.y);
            unsigned long long b6 = pack2(a1.z, a1.z), b7 = pack2(a1.w, a1.w);
            acc2[0][0] = fma2(b0, w2.x, acc2[0][0]); acc2[0][1] = fma2(b0, w2.y, acc2[0][1]);
            acc2[1][0] = fma2(b1, w2.x, acc2[1][0]); acc2[1][1] = fma2(b1, w2.y, acc2[1][1]);
            acc2[2][0] = fma2(b2, w2.x, acc2[2][0]); acc2[2][1] = fma2(b2, w2.y, acc2[2][1]);
            acc2[3][0] = fma2(b3, w2.x, acc2[3][0]); acc2[3][1] = fma2(b3, w2.y, acc2[3][1]);
            acc2[4][0] = fma2(b4, w2.x, acc2[4][0]); acc2[4][1] = fma2(b4, w2.y, acc2[4][1]);
            acc2[5][0] = fma2(b5, w2.x, acc2[5][0]); acc2[5][1] = fma2(b5, w2.y, acc2[5][1]);
            acc2[6][0] = fma2(b6, w2.x, acc2[6][0]); acc2[6][1] = fma2(b6, w2.y, acc2[6][1]);
            acc2[7][0] = fma2(b7, w2.x, acc2[7][0]); acc2[7][1] = fma2(b7, w2.y, acc2[7][1]);
        }
        __syncthreads();
    }
    #pragma unroll
    for (int i = 0; i < 8; i++) {
        int row = rowBase + (ty << 3) + i;
        float2 lo = unpack2(acc2[i][0]), hi = unpack2(acc2[i][1]);
        *(float4*)(outEnc + (long)row * 256 + colBase + (tx << 2)) =
            make_float4(lo.x, lo.y, hi.x, hi.y);
    }
}

// ============================================================
// Attention (champion verbatim; numerics frozen).
// ============================================================
__global__ __launch_bounds__(256, 1) void attn_kernel(const float* __restrict__ dist)
{
    __shared__ float Ks[2][8 * 256];
    __shared__ float Vs[2][8 * 256];
    __shared__ float ds[2][8 * 64];   // [k][q] transposed

    const int b = blockIdx.y;
    const int qbase = blockIdx.x * 64;
    const int t = threadIdx.x;
    const int h = t >> 5, q = t & 31;
    const int drow = t >> 2, dcol = (t & 3) << 1;

    const float* Kg = g_K + (long)b * NN * HIDD;
    const float* Vg = g_V + (long)b * NN * HIDD;
    const float* dg = dist + ((long)(b * NN + qbase + drow)) * NN + dcol;

    unsigned ks_base = (unsigned)__cvta_generic_to_shared(&Ks[0][0]);
    unsigned vs_base = (unsigned)__cvta_generic_to_shared(&Vs[0][0]);

    unsigned long long qa[16], qb[16];
    {
        const ulonglong2* qp0 = (const ulonglong2*)(g_Q + ((long)(b * NN + qbase + q)) * HIDD + (h << 5));
        const ulonglong2* qp1 = (const ulonglong2*)(g_Q + ((long)(b * NN + qbase + q + 32)) * HIDD + (h << 5));
        #pragma unroll
        for (int d4 = 0; d4 < 8; d4++) {
            ulonglong2 v0 = qp0[d4], v1 = qp1[d4];
            qa[2*d4] = v0.x; qa[2*d4+1] = v0.y;
            qb[2*d4] = v1.x; qb[2*d4+1] = v1.y;
        }
    }

    {
        cp16(ks_base + t * 16,             (const char*)Kg + t * 16);
        cp16(ks_base + (t + 256) * 16,     (const char*)Kg + (t + 256) * 16);
        cp16(vs_base + t * 16,             (const char*)Vg + t * 16);
        cp16(vs_base + (t + 256) * 16,     (const char*)Vg + (t + 256) * 16);
        cp_commit();
        float2 d0 = *(const float2*)dg;
        ds[0][dcol * 64 + drow]       = d0.x;
        ds[0][(dcol + 1) * 64 + drow] = d0.y;
        cp_wait0();
    }
    __syncthreads();

    float ma = -1e30f, la = 0.f, mb = -1e30f, lb = 0.f;
    unsigned long long oa[16], ob[16];
    #pragma unroll
    for (int d = 0; d < 16; d++) { oa[d] = 0ull; ob[d] = 0ull; }
    const float scale = 0.1767766952966369f;  // 1/sqrt(32)

    for (int kt = 0; kt < 128; kt++) {
        const int cur = kt & 1;
        float2 pd;
        if (kt < 127) {
            const int nxt = cur ^ 1;
            const char* Kn = (const char*)Kg + (kt + 1) * 8192;
            const char* Vn = (const char*)Vg + (kt + 1) * 8192;
            unsigned ksn = ks_base + nxt * 8192;
            unsigned vsn = vs_base + nxt * 8192;
            cp16(ksn + t * 16,         Kn + t * 16);
            cp16(ksn + (t + 256) * 16, Kn + (t + 256) * 16);
            cp16(vsn + t * 16,         Vn + t * 16);
            cp16(vsn + (t + 256) * 16, Vn + (t + 256) * 16);
            cp_commit();
            pd = *(const float2*)(dg + (kt + 1) * 8);
        }

        const float* Kc = Ks[cur];
        const float* Vc = Vs[cur];
        const float* dc = ds[cur];

        float sva[8], svb[8];
        float smaxa = -1e30f, smaxb = -1e30f;
        #pragma unroll
        for (int kk = 0; kk < 8; kk++) {
            const ulonglong2* kp = (const ulonglong2*)(Kc + kk * 256 + (h << 5));
            unsigned long long accA = 0ull, accB = 0ull, accC = 0ull, accD = 0ull;
            #pragma unroll
            for (int d4 = 0; d4 < 8; d4++) {
                ulonglong2 k2 = kp[d4];
                accA = fma2(qa[2*d4],   k2.x, accA);
                accB = fma2(qa[2*d4+1], k2.y, accB);
                accC = fma2(qb[2*d4],   k2.x, accC);
                accD = fma2(qb[2*d4+1], k2.y, accD);
            }
            float2 fa = unpack2(accA), fb = unpack2(accB);
            float2 fc = unpack2(accC), fd = unpack2(accD);
            float sA = ((fa.x + fa.y) + (fb.x + fb.y)) * scale + dc[kk * 64 + q];
            float sB = ((fc.x + fc.y) + (fd.x + fd.y)) * scale + dc[kk * 64 + 32 + q];
            sva[kk] = sA; svb[kk] = sB;
            smaxa = fmaxf(smaxa, sA);
            smaxb = fmaxf(smaxb, sB);
        }
        float mna = fmaxf(ma, smaxa);
        if (__any_sync(0xFFFFFFFFu, mna > ma)) {
            float corr = __expf(ma - mna);
            la *= corr;
            unsigned long long cc = pack2(corr, corr);
            #pragma unroll
            for (int d = 0; d < 16; d++) oa[d] = mul2(oa[d], cc);
            ma = mna;
        }
        float mnb = fmaxf(mb, smaxb);
        if (__any_sync(0xFFFFFFFFu, mnb > mb)) {
            float corr = __expf(mb - mnb);
            lb *= corr;
            unsigned long long cc = pack2(corr, corr);
            #pragma unroll
            for (int d = 0; d < 16; d++) ob[d] = mul2(ob[d], cc);
            mb = mnb;
        }
        #pragma unroll
        for (int kk = 0; kk < 8; kk++) {
            float pA = __expf(sva[kk] - ma);
            float pB = __expf(svb[kk] - mb);
            la += pA; lb += pB;
            unsigned long long p2a = pack2(pA, pA);
            unsigned long long p2b = pack2(pB, pB);
            const ulonglong2* vp = (const ulonglong2*)(Vc + kk * 256 + (h << 5));
            #pragma unroll
            for (int d4 = 0; d4 < 8; d4++) {
                ulonglong2 v2 = vp[d4];
                oa[2*d4]   = fma2(v2.x, p2a, oa[2*d4]);
                oa[2*d4+1] = fma2(v2.y, p2a, oa[2*d4+1]);
                ob[2*d4]   = fma2(v2.x, p2b, ob[2*d4]);
                ob[2*d4+1] = fma2(v2.y, p2b, ob[2*d4+1]);
            }
        }

        if (kt < 127) {
            const int nxt = cur ^ 1;
            ds[nxt][dcol * 64 + drow]       = pd.x;
            ds[nxt][(dcol + 1) * 64 + drow] = pd.y;
            cp_wait0();
        }
        __syncthreads();
    }

    float inva = 1.f / la, invb = 1.f / lb;
    float* op0 = g_AO + ((long)(b * NN + qbase + q)) * HIDD + (h << 5);
    float* op1 = g_AO + ((long)(b * NN + qbase + q + 32)) * HIDD + (h << 5);
    #pragma unroll
    for (int d4 = 0; d4 < 8; d4++) {
        float2 a0 = unpack2(oa[2*d4]), a1 = unpack2(oa[2*d4+1]);
        float2 b0 = unpack2(ob[2*d4]), b1 = unpack2(ob[2*d4+1]);
        ((float4*)op0)[d4] = make_float4(a0.x * inva, a0.y * inva, a1.x * inva, a1.y * inva);
        ((float4*)op1)[d4] = make_float4(b0.x * invb, b0.y * invb, b1.x * invb, b1.y * invb);
    }
}

// ============================================================
// Node scores from out[OFF_ENC]: s = tanh((x . w) / ||w||).
// ============================================================
__global__ __launch_bounds__(256) void score_kernel(
    const float* __restrict__ enc, const float* __restrict__ w)
{
    int warp = (blockIdx.x * blockDim.x + threadIdx.x) >> 5;
    int lane = threadIdx.x & 31;
    if (warp >= BB * NN) return;
    const float* x = enc + (long)warp * HIDD;
    float sx = 0.f, sw = 0.f;
    #pragma unroll
    for (int i = lane; i < HIDD; i += 32) {
        float wv = w[i];
        sx += x[i] * wv;
        sw += wv * wv;
    }
    #pragma unroll
    for (int off = 16; off; off >>= 1) {
        sx += __shfl_xor_sync(0xFFFFFFFFu, sx, off);
        sw += __shfl_xor_sync(0xFFFFFFFFu, sw, off);
    }
    if (lane == 0) g_score[warp] = tanhf(sx / sqrtf(sw));
}

// ============================================================
// Top-K per graph: bitonic sort of 1024 (desc score, asc index).
// ============================================================
__global__ __launch_bounds__(1024) void topk_kernel(float* __restrict__ out_perm)
{
    __shared__ unsigned long long s[NN];
    const int b = blockIdx.x, t = threadIdx.x;
    float sc = g_score[b * NN + t];
    unsigned u = __float_as_uint(sc);
    u = (u & 0x80000000u) ? ~u : (u | 0x80000000u);
    u = ~u;                                            // descending
    s[t] = (((unsigned long long)u) << 32) | (unsigned)t;
    g_nodemap[b * NN + t] = -1;
    __syncthreads();
    for (unsigned k = 2; k <= NN; k <<= 1)
        for (unsigned j = k >> 1; j; j >>= 1) {
            unsigned i = t, ixj = i ^ j;
            if (ixj > i) {
                bool up = ((i & k) == 0);
                unsigned long long a = s[i], c = s[ixj];
                if ((a > c) == up) { s[i] = c; s[ixj] = a; }
            }
            __syncthreads();
        }
    if (t < KKP) {
        int node = (int)(s[t] & 0xFFFFFFFFu);
        g_perm[b * KKP + t] = node;
        g_vals[b * KKP + t] = g_score[b * NN + node];
        out_perm[b * KKP + t] = (float)node;
        g_nodemap[b * NN + node] = t;
    }
}

// ============================================================
// sub_x gather: 4 rows per block, reads enc from out[OFF_ENC].
// ============================================================
__global__ __launch_bounds__(256) void subx_kernel(
    const float* __restrict__ enc, float* __restrict__ out)
{
    const int row0 = blockIdx.x * 4;
    #pragma unroll
    for (int r = 0; r < 4; r++) {
        int row = row0 + r;
        int b = row / KKP;
        int node = g_perm[row];
        float val = g_vals[row];
        const float* src = enc + ((long)b * NN + node) * HIDD;
        out[(long)row * HIDD + threadIdx.x] = src[threadIdx.x] * val;
    }
}

// ============================================================
// Edge pipeline v2 (2 kernels).
// Valid-edge keys (nu*512+nv, 18 bits) are sorted; invalid edges
// (~75%) all share one constant payload and are emitted as fill.
// Equal keys <=> identical payloads, so key-sort == stable argsort.
// ============================================================
__global__ __launch_bounds__(1024) void edge_build_compact(const void* __restrict__ eiraw)
{
    __shared__ int s_cnt;
    __shared__ int s_is64;
    const int b = blockIdx.x;
    const int t = threadIdx.x;
    if (t == 0) {
        s_cnt = 0;
        const unsigned* w32 = (const unsigned*)eiraw;
        int all0 = 1;
        for (int i = 0; i < 64; i++)
            if (w32[2 * i + 1] != 0u) { all0 = 0; break; }
        s_is64 = all0;
    }
    __syncthreads();
    const int is64 = s_is64;
    const int total = BB * EPER;
    for (int e = t; e < EPER; e += 1024) {
        int idx = b * EPER + e;
        long long vs, vd;
        if (is64) {
            const long long* ei = (const long long*)eiraw;
            vs = ei[idx];
            vd = ei[total + idx];
        } else {
            const int* ei = (const int*)eiraw;
            vs = ei[idx];
            vd = ei[total + idx];
        }
        int src = (int)(vs - (long long)b * NN);
        int dst = (int)(vd - (long long)b * NN);
        src = min(max(src, 0), NN - 1);
        dst = min(max(dst, 0), NN - 1);
        int nu = g_nodemap[b * NN + src];
        int nv = g_nodemap[b * NN + dst];
        if (nu >= 0 && nv >= 0) {
            int slot = atomicAdd(&s_cnt, 1);
            if (slot < ECAP)
                g_ekeys[b * ECAP + slot] = (unsigned)(nu * KKP + nv);
        }
    }
    __syncthreads();
    if (t == 0) g_ecount[b] = min(s_cnt, ECAP);
}

// Sort up to ECAP=8192 keys in 32KB shared; emit all EPER outputs.
__global__ __launch_bounds__(1024) void edge_sort_emit(
    float* __restrict__ out_e, float* __restrict__ out_valid)
{
    __shared__ unsigned sh[ECAP];
    const int b = blockIdx.x, t = threadIdx.x;
    const int n = g_ecount[b];

    for (int i = t; i < ECAP; i += 1024)
        sh[i] = (i < n) ? g_ekeys[b * ECAP + i] : 0xFFFFFFFFu;
    __syncthreads();

    for (unsigned k = 2; k <= ECAP; k <<= 1)
        for (unsigned j = k >> 1; j; j >>= 1) {
            // 4096 active compares; direct index mapping (no idle lanes)
            #pragma unroll 1
            for (int loc = t; loc < ECAP / 2; loc += 1024) {
                unsigned i   = (((unsigned)loc & ~(j - 1)) << 1) | ((unsigned)loc & (j - 1));
                unsigned ixj = i | j;
                bool up = ((i & k) == 0);
                unsigned a = sh[i], c = sh[ixj];
                if ((a > c) == up) { sh[i] = c; sh[ixj] = a; }
            }
            __syncthreads();
        }

    for (int e = t; e < EPER; e += 1024) {
        float fou = -1.f, fov = -1.f, val = 0.f;
        if (e < n) {
            unsigned key = sh[e];
            fou = (float)(int)(key >> 9);
            fov = (float)(int)(key & 511u);
            val = 1.f;
        }
        out_e[(long)b * 2 * EPER + e]        = fou;
        out_e[(long)b * 2 * EPER + EPER + e] = fov;
        out_valid[(long)b * EPER + e]        = val;
    }
}

// ============================================================
extern "C" void kernel_launch(void* const* d_in, const int* in_sizes, int n_in,
                              void* d_out, int out_size)
{
    const float* X    = (const float*)d_in[0];
    const void*  EI   = d_in[1];
    const float* DIST = (const float*)d_in[3];
    const float* Wq   = (const float*)d_in[5];
    const float* Wk   = (const float*)d_in[6];
    const float* Wv   = (const float*)d_in[7];
    const float* Wo   = (const float*)d_in[8];
    const float* tw   = (const float*)d_in[9];
    float* out = (float*)d_out;

    gemm_qkv<<<dim3(4, 64), 256>>>(X, Wq, Wk, Wv);

    attn_kernel<<<dim3(16, 8), 256>>>(DIST);

    gemm_o<<<dim3(4, 64), 256>>>(Wo, out + OFF_ENC);

    score_kernel<<<(BB * NN * 32) / 256, 256>>>(out + OFF_ENC, tw);
    topk_kernel<<<BB, NN>>>(out + OFF_PERM);
    subx_kernel<<<BB * KKP / 4, 256>>>(out + OFF_ENC, out + OFF_SUBX);

    edge_build_compact<<<BB, 1024>>>(EI);
    edge_sort_emit<<<BB, 1024>>>(out + OFF_EDGE, out + OFF_VALID);
}

// round 17
// speedup vs baseline: 1.0941x; 1.0109x over previous
#include <cuda_runtime.h>

#define BB 8
#define NN 1024
#define HIDD 256
#define HEADS 8
#define DHH 32
#define EPER 16384
#define KKP 512
#define ECAP 8192

// ---- output layout (float32, concatenated flattened outputs) ----
#define OFF_ENC   0
#define OFF_SUBX  (BB*NN*HIDD)
#define OFF_EDGE  (OFF_SUBX + BB*KKP*HIDD)
#define OFF_PERM  (OFF_EDGE + BB*2*EPER)
#define OFF_VALID (OFF_PERM + BB*KKP)

// ---- device scratch ----
__device__ float g_Q[BB*NN*HIDD];
__device__ float g_K[BB*NN*HIDD];
__device__ float g_V[BB*NN*HIDD];
__device__ float g_AO[BB*NN*HIDD];
__device__ float g_score[BB*NN];
__device__ int   g_perm[BB*KKP];
__device__ float g_vals[BB*KKP];
__device__ int   g_nodemap[BB*NN];

// ---- packed f32x2 helpers ----
__device__ __forceinline__ unsigned long long fma2(
    unsigned long long a, unsigned long long b, unsigned long long c) {
    unsigned long long d;
    asm("fma.rn.f32x2 %0, %1, %2, %3;" : "=l"(d) : "l"(a), "l"(b), "l"(c));
    return d;
}
__device__ __forceinline__ unsigned long long mul2(
    unsigned long long a, unsigned long long b) {
    unsigned long long d;
    asm("mul.rn.f32x2 %0, %1, %2;" : "=l"(d) : "l"(a), "l"(b));
    return d;
}
__device__ __forceinline__ unsigned long long pack2(float lo, float hi) {
    unsigned long long r;
    asm("mov.b64 %0, {%1, %2};" : "=l"(r) : "f"(lo), "f"(hi));
    return r;
}
__device__ __forceinline__ float2 unpack2(unsigned long long v) {
    float2 r;
    asm("mov.b64 {%0, %1}, %2;" : "=f"(r.x), "=f"(r.y) : "l"(v));
    return r;
}
__device__ __forceinline__ void cp16(unsigned smem, const void* g) {
    asm volatile("cp.async.cg.shared.global [%0], [%1], 16;" :: "r"(smem), "l"(g));
}
__device__ __forceinline__ void cp_commit() {
    asm volatile("cp.async.commit_group;");
}
__device__ __forceinline__ void cp_wait0() {
    asm volatile("cp.async.wait_group 0;");
}

// ============================================================
// Fused QKV GEMM (champion verbatim; numerics frozen).
// ============================================================
__global__ __launch_bounds__(256) void gemm_qkv(
    const float* __restrict__ X, const float* __restrict__ Wq,
    const float* __restrict__ Wk, const float* __restrict__ Wv)
{
    __shared__ float As[16][128];
    __shared__ float Ws[3][16][64];
    const int t  = threadIdx.x;
    const int tx = t & 15;
    const int ty = t >> 4;
    const int rowBase = blockIdx.y * 128;
    const int colBase = blockIdx.x * 64;

    unsigned long long aQ[8][2], aK[8][2], aV[8][2];
    #pragma unroll
    for (int i = 0; i < 8; i++) {
        aQ[i][0] = 0ull; aQ[i][1] = 0ull;
        aK[i][0] = 0ull; aK[i][1] = 0ull;
        aV[i][0] = 0ull; aV[i][1] = 0ull;
    }

    const int wr = t >> 4, wc = (t & 15) << 2;

    for (int k0 = 0; k0 < 256; k0 += 16) {
        #pragma unroll
        for (int li = 0; li < 2; li++) {
            int idx = t * 2 + li;
            int row = idx >> 2;
            int c4  = (idx & 3) << 2;
            float4 a4 = *(const float4*)(X + (rowBase + row) * 256 + k0 + c4);
            As[c4 + 0][row] = a4.x; As[c4 + 1][row] = a4.y;
            As[c4 + 2][row] = a4.z; As[c4 + 3][row] = a4.w;
        }
        *(float4*)(&Ws[0][wr][wc]) = *(const float4*)(Wq + (k0 + wr) * 256 + colBase + wc);
        *(float4*)(&Ws[1][wr][wc]) = *(const float4*)(Wk + (k0 + wr) * 256 + colBase + wc);
        *(float4*)(&Ws[2][wr][wc]) = *(const float4*)(Wv + (k0 + wr) * 256 + colBase + wc);
        __syncthreads();
        #pragma unroll
        for (int kk = 0; kk < 16; kk++) {
            float4 a0 = *(const float4*)(&As[kk][ty << 3]);
            float4 a1 = *(const float4*)(&As[kk][(ty << 3) + 4]);
            unsigned long long b0 = pack2(a0.x, a0.x), b1 = pack2(a0.y, a0.y);
            unsigned long long b2 = pack2(a0.z, a0.z), b3 = pack2(a0.w, a0.w);
            unsigned long long b4 = pack2(a1.x, a1.x), b5 = pack2(a1.y, a1.y);
            unsigned long long b6 = pack2(a1.z, a1.z), b7 = pack2(a1.w, a1.w);
            {
                ulonglong2 w2 = *(const ulonglong2*)(&Ws[0][kk][tx << 2]);
                aQ[0][0] = fma2(b0, w2.x, aQ[0][0]); aQ[0][1] = fma2(b0, w2.y, aQ[0][1]);
                aQ[1][0] = fma2(b1, w2.x, aQ[1][0]); aQ[1][1] = fma2(b1, w2.y, aQ[1][1]);
                aQ[2][0] = fma2(b2, w2.x, aQ[2][0]); aQ[2][1] = fma2(b2, w2.y, aQ[2][1]);
                aQ[3][0] = fma2(b3, w2.x, aQ[3][0]); aQ[3][1] = fma2(b3, w2.y, aQ[3][1]);
                aQ[4][0] = fma2(b4, w2.x, aQ[4][0]); aQ[4][1] = fma2(b4, w2.y, aQ[4][1]);
                aQ[5][0] = fma2(b5, w2.x, aQ[5][0]); aQ[5][1] = fma2(b5, w2.y, aQ[5][1]);
                aQ[6][0] = fma2(b6, w2.x, aQ[6][0]); aQ[6][1] = fma2(b6, w2.y, aQ[6][1]);
                aQ[7][0] = fma2(b7, w2.x, aQ[7][0]); aQ[7][1] = fma2(b7, w2.y, aQ[7][1]);
            }
            {
                ulonglong2 w2 = *(const ulonglong2*)(&Ws[1][kk][tx << 2]);
                aK[0][0] = fma2(b0, w2.x, aK[0][0]); aK[0][1] = fma2(b0, w2.y, aK[0][1]);
                aK[1][0] = fma2(b1, w2.x, aK[1][0]); aK[1][1] = fma2(b1, w2.y, aK[1][1]);
                aK[2][0] = fma2(b2, w2.x, aK[2][0]); aK[2][1] = fma2(b2, w2.y, aK[2][1]);
                aK[3][0] = fma2(b3, w2.x, aK[3][0]); aK[3][1] = fma2(b3, w2.y, aK[3][1]);
                aK[4][0] = fma2(b4, w2.x, aK[4][0]); aK[4][1] = fma2(b4, w2.y, aK[4][1]);
                aK[5][0] = fma2(b5, w2.x, aK[5][0]); aK[5][1] = fma2(b5, w2.y, aK[5][1]);
                aK[6][0] = fma2(b6, w2.x, aK[6][0]); aK[6][1] = fma2(b6, w2.y, aK[6][1]);
                aK[7][0] = fma2(b7, w2.x, aK[7][0]); aK[7][1] = fma2(b7, w2.y, aK[7][1]);
            }
            {
                ulonglong2 w2 = *(const ulonglong2*)(&Ws[2][kk][tx << 2]);
                aV[0][0] = fma2(b0, w2.x, aV[0][0]); aV[0][1] = fma2(b0, w2.y, aV[0][1]);
                aV[1][0] = fma2(b1, w2.x, aV[1][0]); aV[1][1] = fma2(b1, w2.y, aV[1][1]);
                aV[2][0] = fma2(b2, w2.x, aV[2][0]); aV[2][1] = fma2(b2, w2.y, aV[2][1]);
                aV[3][0] = fma2(b3, w2.x, aV[3][0]); aV[3][1] = fma2(b3, w2.y, aV[3][1]);
                aV[4][0] = fma2(b4, w2.x, aV[4][0]); aV[4][1] = fma2(b4, w2.y, aV[4][1]);
                aV[5][0] = fma2(b5, w2.x, aV[5][0]); aV[5][1] = fma2(b5, w2.y, aV[5][1]);
                aV[6][0] = fma2(b6, w2.x, aV[6][0]); aV[6][1] = fma2(b6, w2.y, aV[6][1]);
                aV[7][0] = fma2(b7, w2.x, aV[7][0]); aV[7][1] = fma2(b7, w2.y, aV[7][1]);
            }
        }
        __syncthreads();
    }
    #pragma unroll
    for (int i = 0; i < 8; i++) {
        long off = (long)(rowBase + (ty << 3) + i) * 256 + colBase + (tx << 2);
        float2 lo, hi;
        lo = unpack2(aQ[i][0]); hi = unpack2(aQ[i][1]);
        *(float4*)(g_Q + off) = make_float4(lo.x, lo.y, hi.x, hi.y);
        lo = unpack2(aK[i][0]); hi = unpack2(aK[i][1]);
        *(float4*)(g_K + off) = make_float4(lo.x, lo.y, hi.x, hi.y);
        lo = unpack2(aV[i][0]); hi = unpack2(aV[i][1]);
        *(float4*)(g_V + off) = make_float4(lo.x, lo.y, hi.x, hi.y);
    }
}

// ============================================================
// Output GEMM: enc = g_AO @ Wo -> out only (champion verbatim).
// ============================================================
__global__ __launch_bounds__(256) void gemm_o(
    const float* __restrict__ Wo, float* __restrict__ outEnc)
{
    const float* A = g_AO;
    __shared__ float As[16][128];
    __shared__ float Ws[16][64];
    const int t  = threadIdx.x;
    const int tx = t & 15;
    const int ty = t >> 4;
    const int rowBase = blockIdx.y * 128;
    const int colBase = blockIdx.x * 64;

    unsigned long long acc2[8][2];
    #pragma unroll
    for (int i = 0; i < 8; i++) { acc2[i][0] = 0ull; acc2[i][1] = 0ull; }

    const int wr = t >> 4, wc = (t & 15) << 2;

    for (int k0 = 0; k0 < 256; k0 += 16) {
        #pragma unroll
        for (int li = 0; li < 2; li++) {
            int idx = t * 2 + li;
            int row = idx >> 2;
            int c4  = (idx & 3) << 2;
            float4 a4 = *(const float4*)(A + (rowBase + row) * 256 + k0 + c4);
            As[c4 + 0][row] = a4.x; As[c4 + 1][row] = a4.y;
            As[c4 + 2][row] = a4.z; As[c4 + 3][row] = a4.w;
        }
        *(float4*)(&Ws[wr][wc]) = *(const float4*)(Wo + (k0 + wr) * 256 + colBase + wc);
        __syncthreads();
        #pragma unroll
        for (int kk = 0; kk < 16; kk++) {
            float4 a0 = *(const float4*)(&As[kk][ty << 3]);
            float4 a1 = *(const float4*)(&As[kk][(ty << 3) + 4]);
            ulonglong2 w2 = *(const ulonglong2*)(&Ws[kk][tx << 2]);
            unsigned long long b0 = pack2(a0.x, a0.x), b1 = pack2(a0.y, a0.y);
            unsigned long long b2 = pack2(a0.z, a0.z), b3 = pack2(a0.w, a0.w);
            unsigned long long b4 = pack2(a1.x, a1.x), b5 = pack2(a1.y, a1.y);
            unsigned long long b6 = pack2(a1.z, a1.z), b7 = pack2(a1.w, a1.w);
            acc2[0][0] = fma2(b0, w2.x, acc2[0][0]); acc2[0][1] = fma2(b0, w2.y, acc2[0][1]);
            acc2[1][0] = fma2(b1, w2.x, acc2[1][0]); acc2[1][1] = fma2(b1, w2.y, acc2[1][1]);
            acc2[2][0] = fma2(b2, w2.x, acc2[2][0]); acc2[2][1] = fma2(b2, w2.y, acc2[2][1]);
            acc2[3][0] = fma2(b3, w2.x, acc2[3][0]); acc2[3][1] = fma2(b3, w2.y, acc2[3][1]);
            acc2[4][0] = fma2(b4, w2.x, acc2[4][0]); acc2[4][1] = fma2(b4, w2.y, acc2[4][1]);
            acc2[5][0] = fma2(b5, w2.x, acc2[5][0]); acc2[5][1] = fma2(b5, w2.y, acc2[5][1]);
            acc2[6][0] = fma2(b6, w2.x, acc2[6][0]); acc2[6][1] = fma2(b6, w2.y, acc2[6][1]);
            acc2[7][0] = fma2(b7, w2.x, acc2[7][0]); acc2[7][1] = fma2(b7, w2.y, acc2[7][1]);
        }
        __syncthreads();
    }
    #pragma unroll
    for (int i = 0; i < 8; i++) {
        int row = rowBase + (ty << 3) + i;
        float2 lo = unpack2(acc2[i][0]), hi = unpack2(acc2[i][1]);
        *(float4*)(outEnc + (long)row * 256 + colBase + (tx << 2)) =
            make_float4(lo.x, lo.y, hi.x, hi.y);
    }
}

// ============================================================
// Attention (champion verbatim; numerics frozen).
// ============================================================
__global__ __launch_bounds__(256, 1) void attn_kernel(const float* __restrict__ dist)
{
    __shared__ float Ks[2][8 * 256];
    __shared__ float Vs[2][8 * 256];
    __shared__ float ds[2][8 * 64];   // [k][q] transposed

    const int b = blockIdx.y;
    const int qbase = blockIdx.x * 64;
    const int t = threadIdx.x;
    const int h = t >> 5, q = t & 31;
    const int drow = t >> 2, dcol = (t & 3) << 1;

    const float* Kg = g_K + (long)b * NN * HIDD;
    const float* Vg = g_V + (long)b * NN * HIDD;
    const float* dg = dist + ((long)(b * NN + qbase + drow)) * NN + dcol;

    unsigned ks_base = (unsigned)__cvta_generic_to_shared(&Ks[0][0]);
    unsigned vs_base = (unsigned)__cvta_generic_to_shared(&Vs[0][0]);

    unsigned long long qa[16], qb[16];
    {
        const ulonglong2* qp0 = (const ulonglong2*)(g_Q + ((long)(b * NN + qbase + q)) * HIDD + (h << 5));
        const ulonglong2* qp1 = (const ulonglong2*)(g_Q + ((long)(b * NN + qbase + q + 32)) * HIDD + (h << 5));
        #pragma unroll
        for (int d4 = 0; d4 < 8; d4++) {
            ulonglong2 v0 = qp0[d4], v1 = qp1[d4];
            qa[2*d4] = v0.x; qa[2*d4+1] = v0.y;
            qb[2*d4] = v1.x; qb[2*d4+1] = v1.y;
        }
    }

    {
        cp16(ks_base + t * 16,             (const char*)Kg + t * 16);
        cp16(ks_base + (t + 256) * 16,     (const char*)Kg + (t + 256) * 16);
        cp16(vs_base + t * 16,             (const char*)Vg + t * 16);
        cp16(vs_base + (t + 256) * 16,     (const char*)Vg + (t + 256) * 16);
        cp_commit();
        float2 d0 = *(const float2*)dg;
        ds[0][dcol * 64 + drow]       = d0.x;
        ds[0][(dcol + 1) * 64 + drow] = d0.y;
        cp_wait0();
    }
    __syncthreads();

    float ma = -1e30f, la = 0.f, mb = -1e30f, lb = 0.f;
    unsigned long long oa[16], ob[16];
    #pragma unroll
    for (int d = 0; d < 16; d++) { oa[d] = 0ull; ob[d] = 0ull; }
    const float scale = 0.1767766952966369f;  // 1/sqrt(32)

    for (int kt = 0; kt < 128; kt++) {
        const int cur = kt & 1;
        float2 pd;
        if (kt < 127) {
            const int nxt = cur ^ 1;
            const char* Kn = (const char*)Kg + (kt + 1) * 8192;
            const char* Vn = (const char*)Vg + (kt + 1) * 8192;
            unsigned ksn = ks_base + nxt * 8192;
            unsigned vsn = vs_base + nxt * 8192;
            cp16(ksn + t * 16,         Kn + t * 16);
            cp16(ksn + (t + 256) * 16, Kn + (t + 256) * 16);
            cp16(vsn + t * 16,         Vn + t * 16);
            cp16(vsn + (t + 256) * 16, Vn + (t + 256) * 16);
            cp_commit();
            pd = *(const float2*)(dg + (kt + 1) * 8);
        }

        const float* Kc = Ks[cur];
        const float* Vc = Vs[cur];
        const float* dc = ds[cur];

        float sva[8], svb[8];
        float smaxa = -1e30f, smaxb = -1e30f;
        #pragma unroll
        for (int kk = 0; kk < 8; kk++) {
            const ulonglong2* kp = (const ulonglong2*)(Kc + kk * 256 + (h << 5));
            unsigned long long accA = 0ull, accB = 0ull, accC = 0ull, accD = 0ull;
            #pragma unroll
            for (int d4 = 0; d4 < 8; d4++) {
                ulonglong2 k2 = kp[d4];
                accA = fma2(qa[2*d4],   k2.x, accA);
                accB = fma2(qa[2*d4+1], k2.y, accB);
                accC = fma2(qb[2*d4],   k2.x, accC);
                accD = fma2(qb[2*d4+1], k2.y, accD);
            }
            float2 fa = unpack2(accA), fb = unpack2(accB);
            float2 fc = unpack2(accC), fd = unpack2(accD);
            float sA = ((fa.x + fa.y) + (fb.x + fb.y)) * scale + dc[kk * 64 + q];
            float sB = ((fc.x + fc.y) + (fd.x + fd.y)) * scale + dc[kk * 64 + 32 + q];
            sva[kk] = sA; svb[kk] = sB;
            smaxa = fmaxf(smaxa, sA);
            smaxb = fmaxf(smaxb, sB);
        }
        float mna = fmaxf(ma, smaxa);
        if (__any_sync(0xFFFFFFFFu, mna > ma)) {
            float corr = __expf(ma - mna);
            la *= corr;
            unsigned long long cc = pack2(corr, corr);
            #pragma unroll
            for (int d = 0; d < 16; d++) oa[d] = mul2(oa[d], cc);
            ma = mna;
        }
        float mnb = fmaxf(mb, smaxb);
        if (__any_sync(0xFFFFFFFFu, mnb > mb)) {
            float corr = __expf(mb - mnb);
            lb *= corr;
            unsigned long long cc = pack2(corr, corr);
            #pragma unroll
            for (int d = 0; d < 16; d++) ob[d] = mul2(ob[d], cc);
            mb = mnb;
        }
        #pragma unroll
        for (int kk = 0; kk < 8; kk++) {
            float pA = __expf(sva[kk] - ma);
            float pB = __expf(svb[kk] - mb);
            la += pA; lb += pB;
            unsigned long long p2a = pack2(pA, pA);
            unsigned long long p2b = pack2(pB, pB);
            const ulonglong2* vp = (const ulonglong2*)(Vc + kk * 256 + (h << 5));
            #pragma unroll
            for (int d4 = 0; d4 < 8; d4++) {
                ulonglong2 v2 = vp[d4];
                oa[2*d4]   = fma2(v2.x, p2a, oa[2*d4]);
                oa[2*d4+1] = fma2(v2.y, p2a, oa[2*d4+1]);
                ob[2*d4]   = fma2(v2.x, p2b, ob[2*d4]);
                ob[2*d4+1] = fma2(v2.y, p2b, ob[2*d4+1]);
            }
        }

        if (kt < 127) {
            const int nxt = cur ^ 1;
            ds[nxt][dcol * 64 + drow]       = pd.x;
            ds[nxt][(dcol + 1) * 64 + drow] = pd.y;
            cp_wait0();
        }
        __syncthreads();
    }

    float inva = 1.f / la, invb = 1.f / lb;
    float* op0 = g_AO + ((long)(b * NN + qbase + q)) * HIDD + (h << 5);
    float* op1 = g_AO + ((long)(b * NN + qbase + q + 32)) * HIDD + (h << 5);
    #pragma unroll
    for (int d4 = 0; d4 < 8; d4++) {
        float2 a0 = unpack2(oa[2*d4]), a1 = unpack2(oa[2*d4+1]);
        float2 b0 = unpack2(ob[2*d4]), b1 = unpack2(ob[2*d4+1]);
        ((float4*)op0)[d4] = make_float4(a0.x * inva, a0.y * inva, a1.x * inva, a1.y * inva);
        ((float4*)op1)[d4] = make_float4(b0.x * invb, b0.y * invb, b1.x * invb, b1.y * invb);
    }
}

// ============================================================
// Node scores from out[OFF_ENC] (champion verbatim; order frozen).
// ============================================================
__global__ __launch_bounds__(256) void score_kernel(
    const float* __restrict__ enc, const float* __restrict__ w)
{
    int warp = (blockIdx.x * blockDim.x + threadIdx.x) >> 5;
    int lane = threadIdx.x & 31;
    if (warp >= BB * NN) return;
    const float* x = enc + (long)warp * HIDD;
    float sx = 0.f, sw = 0.f;
    #pragma unroll
    for (int i = lane; i < HIDD; i += 32) {
        float wv = w[i];
        sx += x[i] * wv;
        sw += wv * wv;
    }
    #pragma unroll
    for (int off = 16; off; off >>= 1) {
        sx += __shfl_xor_sync(0xFFFFFFFFu, sx, off);
        sw += __shfl_xor_sync(0xFFFFFFFFu, sw, off);
    }
    if (lane == 0) g_score[warp] = tanhf(sx / sqrtf(sw));
}

// ============================================================
// Top-K: bitonic sort of 1024 (desc score, asc index).
// Steps with j<=16 run in registers via shfl (network equivalent:
// (i&k) is invariant under xor with j<k). Distinct keys => output
// array identical to the previous all-shared implementation.
// ============================================================
__global__ __launch_bounds__(1024) void topk_kernel(float* __restrict__ out_perm)
{
    __shared__ unsigned long long s[NN];
    const int b = blockIdx.x, t = threadIdx.x;
    float sc = g_score[b * NN + t];
    unsigned u = __float_as_uint(sc);
    u = (u & 0x80000000u) ? ~u : (u | 0x80000000u);
    u = ~u;                                            // descending
    unsigned long long v = (((unsigned long long)u) << 32) | (unsigned)t;
    g_nodemap[b * NN + t] = -1;

    // k = 2..32 entirely in-warp
    #pragma unroll
    for (unsigned k = 2; k <= 32; k <<= 1) {
        #pragma unroll
        for (unsigned j = k >> 1; j; j >>= 1) {
            unsigned long long p = __shfl_xor_sync(0xFFFFFFFFu, v, j);
            bool up = ((t & k) == 0);
            bool lowidx = ((t & j) == 0);
            bool takeMin = (lowidx == up);
            v = takeMin ? (v < p ? v : p) : (v > p ? v : p);
        }
    }
    s[t] = v;
    __syncthreads();

    for (unsigned k = 64; k <= 1024; k <<= 1) {
        for (unsigned j = k >> 1; j >= 32; j >>= 1) {
            unsigned i = (unsigned)t, ixj = i ^ j;
            if (ixj > i) {
                bool up = ((i & k) == 0);
                unsigned long long a = s[i], c = s[ixj];
                if ((a > c) == up) { s[i] = c; s[ixj] = a; }
            }
            __syncthreads();
        }
        v = s[t];
        #pragma unroll
        for (unsigned j = 16; j; j >>= 1) {
            unsigned long long p = __shfl_xor_sync(0xFFFFFFFFu, v, j);
            bool up = ((t & k) == 0);
            bool lowidx = ((t & j) == 0);
            bool takeMin = (lowidx == up);
            v = takeMin ? (v < p ? v : p) : (v > p ? v : p);
        }
        s[t] = v;
        __syncthreads();
    }

    if (t < KKP) {
        int node = (int)(s[t] & 0xFFFFFFFFu);
        g_perm[b * KKP + t] = node;
        g_vals[b * KKP + t] = g_score[b * NN + node];
        out_perm[b * KKP + t] = (float)node;
        g_nodemap[b * NN + node] = t;
    }
}

// ============================================================
// sub_x gather (champion verbatim).
// ============================================================
__global__ __launch_bounds__(256) void subx_kernel(
    const float* __restrict__ enc, float* __restrict__ out)
{
    const int row0 = blockIdx.x * 4;
    #pragma unroll
    for (int r = 0; r < 4; r++) {
        int row = row0 + r;
        int b = row / KKP;
        int node = g_perm[row];
        float val = g_vals[row];
        const float* src = enc + ((long)b * NN + node) * HIDD;
        out[(long)row * HIDD + threadIdx.x] = src[threadIdx.x] * val;
    }
}

// ============================================================
// Edge pipeline v3 (1 kernel): build valid keys straight into
// shared, pad, 32-bit bitonic sort, emit. Invalid edges (~75%)
// share one constant payload; key encodes (nu,nv).
// ============================================================
__global__ __launch_bounds__(1024) void edge_kernel(
    const void* __restrict__ eiraw,
    float* __restrict__ out_e, float* __restrict__ out_valid)
{
    __shared__ unsigned sh[ECAP];
    __shared__ int s_cnt;
    __shared__ int s_is64;
    const int b = blockIdx.x;
    const int t = threadIdx.x;
    if (t == 0) {
        s_cnt = 0;
        const unsigned* w32 = (const unsigned*)eiraw;
        int all0 = 1;
        for (int i = 0; i < 64; i++)
            if (w32[2 * i + 1] != 0u) { all0 = 0; break; }
        s_is64 = all0;
    }
    __syncthreads();
    const int is64 = s_is64;
    const int total = BB * EPER;
    for (int e = t; e < EPER; e += 1024) {
        int idx = b * EPER + e;
        long long vs, vd;
        if (is64) {
            const long long* ei = (const long long*)eiraw;
            vs = ei[idx];
            vd = ei[total + idx];
        } else {
            const int* ei = (const int*)eiraw;
            vs = ei[idx];
            vd = ei[total + idx];
        }
        int src = (int)(vs - (long long)b * NN);
        int dst = (int)(vd - (long long)b * NN);
        src = min(max(src, 0), NN - 1);
        dst = min(max(dst, 0), NN - 1);
        int nu = g_nodemap[b * NN + src];
        int nv = g_nodemap[b * NN + dst];
        if (nu >= 0 && nv >= 0) {
            int slot = atomicAdd(&s_cnt, 1);
            if (slot < ECAP)
                sh[slot] = (unsigned)(nu * KKP + nv);
        }
    }
    __syncthreads();
    const int n = min(s_cnt, ECAP);
    for (int i = t; i < ECAP; i += 1024)
        if (i >= n) sh[i] = 0xFFFFFFFFu;
    __syncthreads();

    for (unsigned k = 2; k <= ECAP; k <<= 1)
        for (unsigned j = k >> 1; j; j >>= 1) {
            #pragma unroll 1
            for (int loc = t; loc < ECAP / 2; loc += 1024) {
                unsigned i   = (((unsigned)loc & ~(j - 1)) << 1) | ((unsigned)loc & (j - 1));
                unsigned ixj = i | j;
                bool up = ((i & k) == 0);
                unsigned a = sh[i], c = sh[ixj];
                if ((a > c) == up) { sh[i] = c; sh[ixj] = a; }
            }
            __syncthreads();
        }

    for (int e = t; e < EPER; e += 1024) {
        float fou = -1.f, fov = -1.f, val = 0.f;
        if (e < n) {
            unsigned key = sh[e];
            fou = (float)(int)(key >> 9);
            fov = (float)(int)(key & 511u);
            val = 1.f;
        }
        out_e[(long)b * 2 * EPER + e]        = fou;
        out_e[(long)b * 2 * EPER + EPER + e] = fov;
        out_valid[(long)b * EPER + e]        = val;
    }
}

// ============================================================
extern "C" void kernel_launch(void* const* d_in, const int* in_sizes, int n_in,
                              void* d_out, int out_size)
{
    const float* X    = (const float*)d_in[0];
    const void*  EI   = d_in[1];
    const float* DIST = (const float*)d_in[3];
    const float* Wq   = (const float*)d_in[5];
    const float* Wk   = (const float*)d_in[6];
    const float* Wv   = (const float*)d_in[7];
    const float* Wo   = (const float*)d_in[8];
    const float* tw   = (const float*)d_in[9];
    float* out = (float*)d_out;

    gemm_qkv<<<dim3(4, 64), 256>>>(X, Wq, Wk, Wv);

    attn_kernel<<<dim3(16, 8), 256>>>(DIST);

    gemm_o<<<dim3(4, 64), 256>>>(Wo, out + OFF_ENC);

    score_kernel<<<(BB * NN * 32) / 256, 256>>>(out + OFF_ENC, tw);
    topk_kernel<<<BB, NN>>>(out + OFF_PERM);
    subx_kernel<<<BB * KKP / 4, 256>>>(out + OFF_ENC, out + OFF_SUBX);

    edge_kernel<<<BB, 1024>>>(EI, out + OFF_EDGE, out + OFF_VALID);
}